// round 1
// baseline (speedup 1.0000x reference)
#include <cuda_runtime.h>

#define B_   2
#define T_   2048
#define DM_  1024
#define H_   16
#define DH_  64
#define BT_  (B_ * T_)   // 4096

// Scratch (allocation-free rule: device globals)
__device__ float g_q[BT_ * DM_];
__device__ float g_k[BT_ * DM_];
__device__ float g_v[BT_ * DM_];
__device__ float g_z[BT_ * DM_];

// ---------------------------------------------------------------------------
// SGEMM: C[M,N] = A[M,K] * W[K,N], row-major. BM=BN=128, BK=8, 256 threads,
// 8x8 micro-tile per thread. M,N,K multiples of 128/128/8 (true here).
// ---------------------------------------------------------------------------
__global__ __launch_bounds__(256) void gemm_nn(
    const float* __restrict__ A, const float* __restrict__ W,
    float* __restrict__ C, int M, int N, int K)
{
    __shared__ float As[8][132];   // [k][m], padded
    __shared__ float Bs[8][128];   // [k][n]

    const int tid = threadIdx.x;
    const int bm0 = blockIdx.y * 128;
    const int bn0 = blockIdx.x * 128;
    const int ty  = tid >> 4;      // 0..15
    const int tx  = tid & 15;      // 0..15

    const int am = tid >> 1;            // 0..127
    const int ak = (tid & 1) * 4;       // 0 or 4
    const int bk = tid >> 5;            // 0..7
    const int bn = (tid & 31) * 4;      // 0..124

    const float* Aptr = A + (size_t)(bm0 + am) * K + ak;
    const float* Bptr = W + (size_t)bk * N + bn0 + bn;

    float acc[8][8];
    #pragma unroll
    for (int i = 0; i < 8; i++)
        #pragma unroll
        for (int j = 0; j < 8; j++) acc[i][j] = 0.f;

    for (int k0 = 0; k0 < K; k0 += 8) {
        float4 a = *(const float4*)(Aptr + k0);
        float4 b = *(const float4*)(Bptr + (size_t)k0 * N);
        __syncthreads();
        As[ak + 0][am] = a.x;
        As[ak + 1][am] = a.y;
        As[ak + 2][am] = a.z;
        As[ak + 3][am] = a.w;
        *(float4*)&Bs[bk][bn] = b;
        __syncthreads();

        #pragma unroll
        for (int kk = 0; kk < 8; kk++) {
            float ra[8], rb[8];
            *(float4*)&ra[0] = *(const float4*)&As[kk][ty * 8];
            *(float4*)&ra[4] = *(const float4*)&As[kk][ty * 8 + 4];
            *(float4*)&rb[0] = *(const float4*)&Bs[kk][tx * 8];
            *(float4*)&rb[4] = *(const float4*)&Bs[kk][tx * 8 + 4];
            #pragma unroll
            for (int i = 0; i < 8; i++)
                #pragma unroll
                for (int j = 0; j < 8; j++)
                    acc[i][j] += ra[i] * rb[j];
        }
    }

    #pragma unroll
    for (int i = 0; i < 8; i++) {
        float* cp = C + (size_t)(bm0 + ty * 8 + i) * N + bn0 + tx * 8;
        *(float4*)(cp)     = make_float4(acc[i][0], acc[i][1], acc[i][2], acc[i][3]);
        *(float4*)(cp + 4) = make_float4(acc[i][4], acc[i][5], acc[i][6], acc[i][7]);
    }
}

// ---------------------------------------------------------------------------
// RoPE in-place on q and k. One thread per (bt, h, pair).
// ---------------------------------------------------------------------------
__global__ void rope_qk(float* __restrict__ q, float* __restrict__ k,
                        const float* __restrict__ cs, const float* __restrict__ sn)
{
    int idx = blockIdx.x * blockDim.x + threadIdx.x;   // 0 .. BT_*H_*32-1
    int i  = idx & 31;
    int h  = (idx >> 5) & (H_ - 1);
    int bt = idx >> 9;
    int t  = bt & (T_ - 1);
    float c = cs[t * 32 + i];
    float s = sn[t * 32 + i];
    size_t base = (size_t)bt * DM_ + h * DH_ + 2 * i;
    float2 qv = *(float2*)(q + base);
    float2 kv = *(float2*)(k + base);
    *(float2*)(q + base) = make_float2(qv.x * c - qv.y * s, qv.x * s + qv.y * c);
    *(float2*)(k + base) = make_float2(kv.x * c - kv.y * s, kv.x * s + kv.y * c);
}

// ---------------------------------------------------------------------------
// Flash attention, causal. Block = (q-tile of 128 rows, one (b,h)).
// 256 threads: ty=tid/16 owns 8 q-rows, tx=tid%16 owns 4 cols.
// k-tiles of 64; online softmax in registers; P staged via smem.
// ---------------------------------------------------------------------------
__global__ __launch_bounds__(256, 2) void attn_kernel(
    const float* __restrict__ q, const float* __restrict__ k,
    const float* __restrict__ v, float* __restrict__ z)
{
    extern __shared__ float sm[];
    float* Qst = sm;                    // [64][132]  (d, m)
    float* Kst = Qst + 64 * 132;        // [64][68]   (d, n)
    float* Vs  = Kst + 64 * 68;         // [64][68]   (kk, d)
    float* Ps  = Vs  + 64 * 68;         // [128][68]  (m, kk)

    const int tid = threadIdx.x;
    const int qi  = 15 - blockIdx.x;          // heavy tiles first
    const int bh  = blockIdx.y;
    const int b   = bh >> 4;
    const int h   = bh & (H_ - 1);
    const int q0  = qi * 128;
    const int ty  = tid >> 4;
    const int tx  = tid & 15;

    const size_t rowoff = (size_t)(b * T_) * DM_ + h * DH_;

    // Load Q tile transposed: Qst[d][m]
    #pragma unroll
    for (int r = 0; r < 8; r++) {
        int lin = tid + r * 256;      // 0..2047
        int m   = lin >> 4;
        int dq  = (lin & 15) * 4;
        float4 qv = *(const float4*)(q + rowoff + (size_t)(q0 + m) * DM_ + dq);
        Qst[(dq + 0) * 132 + m] = qv.x;
        Qst[(dq + 1) * 132 + m] = qv.y;
        Qst[(dq + 2) * 132 + m] = qv.z;
        Qst[(dq + 3) * 132 + m] = qv.w;
    }

    float o[8][4];
    float mrow[8], lrow[8];
    #pragma unroll
    for (int i = 0; i < 8; i++) {
        mrow[i] = -1e30f;
        lrow[i] = 0.f;
        #pragma unroll
        for (int j = 0; j < 4; j++) o[i][j] = 0.f;
    }

    const int nkt = 2 * qi + 2;     // causal: tiles up to and including diagonal

    for (int kt = 0; kt < nkt; kt++) {
        const int k0 = kt * 64;
        __syncthreads();   // previous iter's PV done (also fences Qst on iter 0)

        // Load K tile transposed + V tile
        #pragma unroll
        for (int r = 0; r < 4; r++) {
            int lin = tid + r * 256;    // 0..1023
            int n   = lin >> 4;
            int dq  = (lin & 15) * 4;
            float4 kv = *(const float4*)(k + rowoff + (size_t)(k0 + n) * DM_ + dq);
            Kst[(dq + 0) * 68 + n] = kv.x;
            Kst[(dq + 1) * 68 + n] = kv.y;
            Kst[(dq + 2) * 68 + n] = kv.z;
            Kst[(dq + 3) * 68 + n] = kv.w;
            float4 vv = *(const float4*)(v + rowoff + (size_t)(k0 + n) * DM_ + dq);
            *(float4*)&Vs[n * 68 + dq] = vv;
        }
        __syncthreads();

        // S = Q K^T
        float s[8][4];
        #pragma unroll
        for (int i = 0; i < 8; i++)
            #pragma unroll
            for (int j = 0; j < 4; j++) s[i][j] = 0.f;

        #pragma unroll 4
        for (int d = 0; d < 64; d++) {
            float ra[8];
            *(float4*)&ra[0] = *(const float4*)&Qst[d * 132 + ty * 8];
            *(float4*)&ra[4] = *(const float4*)&Qst[d * 132 + ty * 8 + 4];
            float4 rb = *(const float4*)&Kst[d * 68 + tx * 4];
            #pragma unroll
            for (int i = 0; i < 8; i++) {
                s[i][0] += ra[i] * rb.x;
                s[i][1] += ra[i] * rb.y;
                s[i][2] += ra[i] * rb.z;
                s[i][3] += ra[i] * rb.w;
            }
        }

        // scale + causal mask
        #pragma unroll
        for (int i = 0; i < 8; i++) {
            int qg = q0 + ty * 8 + i;
            #pragma unroll
            for (int j = 0; j < 4; j++) {
                int kg = k0 + tx * 4 + j;
                s[i][j] = (kg <= qg) ? s[i][j] * 0.125f : -1e30f;
            }
        }

        // online softmax (row reduce across 16 tx lanes)
        #pragma unroll
        for (int i = 0; i < 8; i++) {
            float mx = fmaxf(fmaxf(s[i][0], s[i][1]), fmaxf(s[i][2], s[i][3]));
            mx = fmaxf(mx, __shfl_xor_sync(0xffffffffu, mx, 1));
            mx = fmaxf(mx, __shfl_xor_sync(0xffffffffu, mx, 2));
            mx = fmaxf(mx, __shfl_xor_sync(0xffffffffu, mx, 4));
            mx = fmaxf(mx, __shfl_xor_sync(0xffffffffu, mx, 8));
            float nm   = fmaxf(mrow[i], mx);
            float corr = __expf(mrow[i] - nm);
            mrow[i] = nm;
            float ps = 0.f;
            #pragma unroll
            for (int j = 0; j < 4; j++) {
                float p = __expf(s[i][j] - nm);
                s[i][j] = p;
                ps += p;
            }
            ps += __shfl_xor_sync(0xffffffffu, ps, 1);
            ps += __shfl_xor_sync(0xffffffffu, ps, 2);
            ps += __shfl_xor_sync(0xffffffffu, ps, 4);
            ps += __shfl_xor_sync(0xffffffffu, ps, 8);
            lrow[i] = lrow[i] * corr + ps;
            #pragma unroll
            for (int j = 0; j < 4; j++) o[i][j] *= corr;
        }

        // stage P
        #pragma unroll
        for (int i = 0; i < 8; i++)
            *(float4*)&Ps[(ty * 8 + i) * 68 + tx * 4] =
                make_float4(s[i][0], s[i][1], s[i][2], s[i][3]);
        __syncthreads();

        // O += P V
        #pragma unroll 2
        for (int kk = 0; kk < 64; kk += 4) {
            float rv[4][4];
            *(float4*)&rv[0][0] = *(const float4*)&Vs[(kk + 0) * 68 + tx * 4];
            *(float4*)&rv[1][0] = *(const float4*)&Vs[(kk + 1) * 68 + tx * 4];
            *(float4*)&rv[2][0] = *(const float4*)&Vs[(kk + 2) * 68 + tx * 4];
            *(float4*)&rv[3][0] = *(const float4*)&Vs[(kk + 3) * 68 + tx * 4];
            #pragma unroll
            for (int i = 0; i < 8; i++) {
                float4 rp = *(const float4*)&Ps[(ty * 8 + i) * 68 + kk];
                #pragma unroll
                for (int j = 0; j < 4; j++)
                    o[i][j] += rp.x * rv[0][j] + rp.y * rv[1][j]
                             + rp.z * rv[2][j] + rp.w * rv[3][j];
            }
        }
    }

    // normalize + write z[b, q0+m, h*64 + tx*4 + j]
    #pragma unroll
    for (int i = 0; i < 8; i++) {
        float inv = 1.f / lrow[i];
        int m = q0 + ty * 8 + i;
        *(float4*)(z + rowoff + (size_t)m * DM_ + tx * 4) =
            make_float4(o[i][0] * inv, o[i][1] * inv, o[i][2] * inv, o[i][3] * inv);
    }
}

// ---------------------------------------------------------------------------
extern "C" void kernel_launch(void* const* d_in, const int* in_sizes, int n_in,
                              void* d_out, int out_size)
{
    const float* x  = (const float*)d_in[0];
    const float* cs = (const float*)d_in[1];
    const float* sn = (const float*)d_in[2];
    const float* Wq = (const float*)d_in[3];
    const float* Wk = (const float*)d_in[4];
    const float* Wv = (const float*)d_in[5];
    const float* Wo = (const float*)d_in[6];
    float* out = (float*)d_out;

    float *qp, *kp, *vp, *zp;
    cudaGetSymbolAddress((void**)&qp, g_q);
    cudaGetSymbolAddress((void**)&kp, g_k);
    cudaGetSymbolAddress((void**)&vp, g_v);
    cudaGetSymbolAddress((void**)&zp, g_z);

    dim3 ggrid(DM_ / 128, BT_ / 128);   // (8, 32)
    gemm_nn<<<ggrid, 256>>>(x, Wq, qp, BT_, DM_, DM_);
    gemm_nn<<<ggrid, 256>>>(x, Wk, kp, BT_, DM_, DM_);
    gemm_nn<<<ggrid, 256>>>(x, Wv, vp, BT_, DM_, DM_);

    rope_qk<<<(BT_ * H_ * 32) / 256, 256>>>(qp, kp, cs, sn);

    const int SMEM = (64 * 132 + 64 * 68 + 64 * 68 + 128 * 68) * 4;  // 103,424 B
    cudaFuncSetAttribute(attn_kernel,
                         cudaFuncAttributeMaxDynamicSharedMemorySize, SMEM);
    attn_kernel<<<dim3(T_ / 128, B_ * H_), 256, SMEM>>>(qp, kp, vp, zp);

    gemm_nn<<<ggrid, 256>>>(zp, Wo, out, BT_, DM_, DM_);
}

// round 3
// speedup vs baseline: 1.4837x; 1.4837x over previous
#include <cuda_runtime.h>
#include <cuda_bf16.h>
#include <cstdint>

#define B_   2
#define T_   2048
#define DM_  1024
#define H_   16
#define DH_  64
#define BT_  (B_ * T_)   // 4096

// Scratch (allocation-free rule: device globals)
__device__ float g_q[BT_ * DM_];
__device__ float g_k[BT_ * DM_];
__device__ float g_v[BT_ * DM_];
__device__ float g_z[BT_ * DM_];
__device__ __nv_bfloat16 g_ah[BT_ * DM_];   // activation hi (x, later z)
__device__ __nv_bfloat16 g_al[BT_ * DM_];   // activation lo
__device__ __nv_bfloat16 g_bh[DM_ * DM_];   // W^T hi
__device__ __nv_bfloat16 g_bl[DM_ * DM_];   // W^T lo

// ===========================================================================
// Warp-MMA helpers (baseline PTX — no tcgen05, harness targets compute_103)
// ===========================================================================
__device__ __forceinline__ uint32_t smem_u32(const void* p) {
    uint32_t a;
    asm("{ .reg .u64 t; cvta.to.shared.u64 t, %1; cvt.u32.u64 %0, t; }"
        : "=r"(a) : "l"(p));
    return a;
}

__device__ __forceinline__ void ldsm4(uint32_t* r, uint32_t addr) {
    asm volatile("ldmatrix.sync.aligned.m8n8.x4.shared.b16 {%0,%1,%2,%3}, [%4];"
                 : "=r"(r[0]), "=r"(r[1]), "=r"(r[2]), "=r"(r[3]) : "r"(addr));
}

__device__ __forceinline__ void mma16816(float* c, const uint32_t* a,
                                         const uint32_t* b) {
    asm volatile(
        "mma.sync.aligned.m16n8k16.row.col.f32.bf16.bf16.f32 "
        "{%0,%1,%2,%3}, {%4,%5,%6,%7}, {%8,%9}, {%0,%1,%2,%3};"
        : "+f"(c[0]), "+f"(c[1]), "+f"(c[2]), "+f"(c[3])
        : "r"(a[0]), "r"(a[1]), "r"(a[2]), "r"(a[3]), "r"(b[0]), "r"(b[1]));
}

// ===========================================================================
// Conversion kernels (fp32 -> bf16 hi/lo split)
// ===========================================================================
__global__ void conv_split(const float* __restrict__ in,
                           __nv_bfloat16* __restrict__ hi,
                           __nv_bfloat16* __restrict__ lo) {
    int i = (blockIdx.x * 256 + threadIdx.x) * 4;
    float4 v = *(const float4*)(in + i);
    float a[4] = {v.x, v.y, v.z, v.w};
    union { unsigned short u[4]; uint2 q; } ph, pl;
    #pragma unroll
    for (int j = 0; j < 4; j++) {
        __nv_bfloat16 h = __float2bfloat16(a[j]);
        float r = a[j] - __bfloat162float(h);
        __nv_bfloat16 l = __float2bfloat16(r);
        ph.u[j] = *(unsigned short*)&h;
        pl.u[j] = *(unsigned short*)&l;
    }
    *(uint2*)(hi + i) = ph.q;
    *(uint2*)(lo + i) = pl.q;
}

// W [K=1024, N=1024] row-major -> Wt hi/lo [N, K] bf16 (transposed split)
__global__ void conv_T(const float* __restrict__ W,
                       __nv_bfloat16* __restrict__ th,
                       __nv_bfloat16* __restrict__ tl) {
    __shared__ float t[32][33];
    const int n0 = blockIdx.x * 32, k0 = blockIdx.y * 32;
    const int tx = threadIdx.x, ty = threadIdx.y;   // (32, 8)
    #pragma unroll
    for (int r = 0; r < 4; r++)
        t[ty * 4 + r][tx] = W[(size_t)(k0 + ty * 4 + r) * DM_ + n0 + tx];
    __syncthreads();
    #pragma unroll
    for (int r = 0; r < 4; r++) {
        float v = t[tx][ty * 4 + r];
        __nv_bfloat16 h = __float2bfloat16(v);
        __nv_bfloat16 l = __float2bfloat16(v - __bfloat162float(h));
        size_t o = (size_t)(n0 + ty * 4 + r) * DM_ + k0 + tx;
        th[o] = h;
        tl[o] = l;
    }
}

// ===========================================================================
// bf16x2-split GEMM via mma.sync (3 passes): C = A * W
//   A as Ah/Al [M,K] row-major bf16, B as Bh/Bl [N,K] (W^T) bf16.
//   CTA tile 128x64, 8 warps of 32x32, BK=32, double-buffered SMEM.
//   SMEM tiles use 80B row pitch (40 bf16) -> conflict-free STS/ldmatrix.
// ===========================================================================
#define STG_A   10240             // bytes per A operand tile (128*80)
#define STG_B   5120              // bytes per B operand tile (64*80)
#define STG_SZ  (2*STG_A + 2*STG_B)  // 30720 per stage

__global__ __launch_bounds__(256) void gemm_mma(
    const __nv_bfloat16* __restrict__ Ah, const __nv_bfloat16* __restrict__ Al,
    const __nv_bfloat16* __restrict__ Bh, const __nv_bfloat16* __restrict__ Bl,
    float* __restrict__ C)
{
    extern __shared__ __align__(16) char sm[];
    const int tid  = threadIdx.x;
    const int wid  = tid >> 5;
    const int lane = tid & 31;
    const int wm   = wid & 3;        // warp M index (0..3)
    const int wn   = wid >> 2;       // warp N index (0..1)
    const int m0   = blockIdx.y * 128;
    const int n0   = blockIdx.x * 64;
    const uint32_t sbase = smem_u32(sm);

    const __nv_bfloat16* gAh = Ah + (size_t)m0 * DM_;
    const __nv_bfloat16* gAl = Al + (size_t)m0 * DM_;
    const __nv_bfloat16* gBh = Bh + (size_t)n0 * DM_;
    const __nv_bfloat16* gBl = Bl + (size_t)n0 * DM_;

    const int arow = tid >> 2;        // 0..63
    const int acg  = tid & 3;         // 16B column group

    // ldmatrix lane offsets (bytes)
    const uint32_t a_off = (uint32_t)((lane & 15) * 80 + (lane >> 4) * 16);
    const uint32_t b_off = (uint32_t)((((lane >> 4) * 8) + (lane & 7)) * 80 +
                                      ((lane >> 3) & 1) * 16);

    float acc[2][4][4];
    #pragma unroll
    for (int i = 0; i < 2; i++)
        #pragma unroll
        for (int j = 0; j < 4; j++)
            #pragma unroll
            for (int l = 0; l < 4; l++) acc[i][j][l] = 0.f;

    uint4 ra0, ra1, rl0, rl1, rbh, rbl;

    #define LDG_CHUNK(k0_)                                                    \
        ra0 = *(const uint4*)(gAh + (size_t)arow        * DM_ + (k0_) + acg * 8); \
        ra1 = *(const uint4*)(gAh + (size_t)(arow + 64) * DM_ + (k0_) + acg * 8); \
        rl0 = *(const uint4*)(gAl + (size_t)arow        * DM_ + (k0_) + acg * 8); \
        rl1 = *(const uint4*)(gAl + (size_t)(arow + 64) * DM_ + (k0_) + acg * 8); \
        rbh = *(const uint4*)(gBh + (size_t)arow        * DM_ + (k0_) + acg * 8); \
        rbl = *(const uint4*)(gBl + (size_t)arow        * DM_ + (k0_) + acg * 8);

    #define STS_CHUNK(st_)                                                    \
        {                                                                     \
            char* p = sm + (st_) * STG_SZ;                                    \
            *(uint4*)(p +            arow * 80        + acg * 16) = ra0;      \
            *(uint4*)(p +           (arow + 64) * 80  + acg * 16) = ra1;      \
            *(uint4*)(p + STG_A +    arow * 80        + acg * 16) = rl0;      \
            *(uint4*)(p + STG_A +   (arow + 64) * 80  + acg * 16) = rl1;      \
            *(uint4*)(p + 2*STG_A +  arow * 80        + acg * 16) = rbh;      \
            *(uint4*)(p + 2*STG_A + STG_B + arow * 80 + acg * 16) = rbl;      \
        }

    LDG_CHUNK(0);
    STS_CHUNK(0);
    __syncthreads();

    for (int c = 0; c < DM_ / 32; c++) {
        if (c + 1 < DM_ / 32) { LDG_CHUNK((c + 1) * 32); }

        const uint32_t stb = sbase + (c & 1) * STG_SZ;
        #pragma unroll
        for (int ks = 0; ks < 2; ks++) {
            uint32_t ah[2][4], al[2][4], bh[4][2], bl[4][2];
            #pragma unroll
            for (int mt = 0; mt < 2; mt++) {
                uint32_t ab = stb + (uint32_t)((wm * 32 + mt * 16) * 80 + ks * 32) + a_off;
                ldsm4(ah[mt], ab);
                ldsm4(al[mt], ab + STG_A);
            }
            #pragma unroll
            for (int bt = 0; bt < 2; bt++) {
                uint32_t bb = stb + 2 * STG_A +
                              (uint32_t)((wn * 32 + bt * 16) * 80 + ks * 32) + b_off;
                uint32_t t0[4], t1[4];
                ldsm4(t0, bb);
                ldsm4(t1, bb + STG_B);
                bh[bt*2][0] = t0[0]; bh[bt*2][1] = t0[1];
                bh[bt*2+1][0] = t0[2]; bh[bt*2+1][1] = t0[3];
                bl[bt*2][0] = t1[0]; bl[bt*2][1] = t1[1];
                bl[bt*2+1][0] = t1[2]; bl[bt*2+1][1] = t1[3];
            }
            #pragma unroll
            for (int mt = 0; mt < 2; mt++)
                #pragma unroll
                for (int nt = 0; nt < 4; nt++) {
                    mma16816(acc[mt][nt], ah[mt], bh[nt]);   // hi*hi
                    mma16816(acc[mt][nt], ah[mt], bl[nt]);   // hi*lo
                    mma16816(acc[mt][nt], al[mt], bh[nt]);   // lo*hi
                }
        }

        if (c + 1 < DM_ / 32) {
            __syncthreads();
            STS_CHUNK((c + 1) & 1);
            __syncthreads();
        }
    }

    // epilogue
    #pragma unroll
    for (int mt = 0; mt < 2; mt++) {
        int m = m0 + wm * 32 + mt * 16 + (lane >> 2);
        #pragma unroll
        for (int nt = 0; nt < 4; nt++) {
            int n = n0 + wn * 32 + nt * 8 + (lane & 3) * 2;
            *(float2*)(C + (size_t)m * DM_ + n) =
                make_float2(acc[mt][nt][0], acc[mt][nt][1]);
            *(float2*)(C + (size_t)(m + 8) * DM_ + n) =
                make_float2(acc[mt][nt][2], acc[mt][nt][3]);
        }
    }
    #undef LDG_CHUNK
    #undef STS_CHUNK
}

// ---------------------------------------------------------------------------
// RoPE in-place on q and k. One thread per (bt, h, pair).
// ---------------------------------------------------------------------------
__global__ void rope_qk(float* __restrict__ q, float* __restrict__ k,
                        const float* __restrict__ cs, const float* __restrict__ sn)
{
    int idx = blockIdx.x * blockDim.x + threadIdx.x;
    int i  = idx & 31;
    int h  = (idx >> 5) & (H_ - 1);
    int bt = idx >> 9;
    int t  = bt & (T_ - 1);
    float c = cs[t * 32 + i];
    float s = sn[t * 32 + i];
    size_t base = (size_t)bt * DM_ + h * DH_ + 2 * i;
    float2 qv = *(float2*)(q + base);
    float2 kv = *(float2*)(k + base);
    *(float2*)(q + base) = make_float2(qv.x * c - qv.y * s, qv.x * s + qv.y * c);
    *(float2*)(k + base) = make_float2(kv.x * c - kv.y * s, kv.x * s + kv.y * c);
}

// ---------------------------------------------------------------------------
// Flash attention, causal (SIMT fp32) — unchanged.
// ---------------------------------------------------------------------------
__global__ __launch_bounds__(256, 2) void attn_kernel(
    const float* __restrict__ q, const float* __restrict__ k,
    const float* __restrict__ v, float* __restrict__ z)
{
    extern __shared__ float smf[];
    float* Qst = smf;                   // [64][132]  (d, m)
    float* Kst = Qst + 64 * 132;        // [64][68]   (d, n)
    float* Vs  = Kst + 64 * 68;         // [64][68]   (kk, d)
    float* Ps  = Vs  + 64 * 68;         // [128][68]  (m, kk)

    const int tid = threadIdx.x;
    const int qi  = 15 - blockIdx.x;
    const int bh  = blockIdx.y;
    const int b   = bh >> 4;
    const int h   = bh & (H_ - 1);
    const int q0  = qi * 128;
    const int ty  = tid >> 4;
    const int tx  = tid & 15;

    const size_t rowoff = (size_t)(b * T_) * DM_ + h * DH_;

    #pragma unroll
    for (int r = 0; r < 8; r++) {
        int lin = tid + r * 256;
        int m   = lin >> 4;
        int dq  = (lin & 15) * 4;
        float4 qv = *(const float4*)(q + rowoff + (size_t)(q0 + m) * DM_ + dq);
        Qst[(dq + 0) * 132 + m] = qv.x;
        Qst[(dq + 1) * 132 + m] = qv.y;
        Qst[(dq + 2) * 132 + m] = qv.z;
        Qst[(dq + 3) * 132 + m] = qv.w;
    }

    float o[8][4];
    float mrow[8], lrow[8];
    #pragma unroll
    for (int i = 0; i < 8; i++) {
        mrow[i] = -1e30f;
        lrow[i] = 0.f;
        #pragma unroll
        for (int j = 0; j < 4; j++) o[i][j] = 0.f;
    }

    const int nkt = 2 * qi + 2;

    for (int kt = 0; kt < nkt; kt++) {
        const int k0 = kt * 64;
        __syncthreads();

        #pragma unroll
        for (int r = 0; r < 4; r++) {
            int lin = tid + r * 256;
            int n   = lin >> 4;
            int dq  = (lin & 15) * 4;
            float4 kv = *(const float4*)(k + rowoff + (size_t)(k0 + n) * DM_ + dq);
            Kst[(dq + 0) * 68 + n] = kv.x;
            Kst[(dq + 1) * 68 + n] = kv.y;
            Kst[(dq + 2) * 68 + n] = kv.z;
            Kst[(dq + 3) * 68 + n] = kv.w;
            float4 vv = *(const float4*)(v + rowoff + (size_t)(k0 + n) * DM_ + dq);
            *(float4*)&Vs[n * 68 + dq] = vv;
        }
        __syncthreads();

        float s[8][4];
        #pragma unroll
        for (int i = 0; i < 8; i++)
            #pragma unroll
            for (int j = 0; j < 4; j++) s[i][j] = 0.f;

        #pragma unroll 4
        for (int d = 0; d < 64; d++) {
            float ra[8];
            *(float4*)&ra[0] = *(const float4*)&Qst[d * 132 + ty * 8];
            *(float4*)&ra[4] = *(const float4*)&Qst[d * 132 + ty * 8 + 4];
            float4 rb = *(const float4*)&Kst[d * 68 + tx * 4];
            #pragma unroll
            for (int i = 0; i < 8; i++) {
                s[i][0] += ra[i] * rb.x;
                s[i][1] += ra[i] * rb.y;
                s[i][2] += ra[i] * rb.z;
                s[i][3] += ra[i] * rb.w;
            }
        }

        #pragma unroll
        for (int i = 0; i < 8; i++) {
            int qg = q0 + ty * 8 + i;
            #pragma unroll
            for (int j = 0; j < 4; j++) {
                int kg = k0 + tx * 4 + j;
                s[i][j] = (kg <= qg) ? s[i][j] * 0.125f : -1e30f;
            }
        }

        #pragma unroll
        for (int i = 0; i < 8; i++) {
            float mx = fmaxf(fmaxf(s[i][0], s[i][1]), fmaxf(s[i][2], s[i][3]));
            mx = fmaxf(mx, __shfl_xor_sync(0xffffffffu, mx, 1));
            mx = fmaxf(mx, __shfl_xor_sync(0xffffffffu, mx, 2));
            mx = fmaxf(mx, __shfl_xor_sync(0xffffffffu, mx, 4));
            mx = fmaxf(mx, __shfl_xor_sync(0xffffffffu, mx, 8));
            float nm   = fmaxf(mrow[i], mx);
            float corr = __expf(mrow[i] - nm);
            mrow[i] = nm;
            float ps = 0.f;
            #pragma unroll
            for (int j = 0; j < 4; j++) {
                float p = __expf(s[i][j] - nm);
                s[i][j] = p;
                ps += p;
            }
            ps += __shfl_xor_sync(0xffffffffu, ps, 1);
            ps += __shfl_xor_sync(0xffffffffu, ps, 2);
            ps += __shfl_xor_sync(0xffffffffu, ps, 4);
            ps += __shfl_xor_sync(0xffffffffu, ps, 8);
            lrow[i] = lrow[i] * corr + ps;
            #pragma unroll
            for (int j = 0; j < 4; j++) o[i][j] *= corr;
        }

        #pragma unroll
        for (int i = 0; i < 8; i++)
            *(float4*)&Ps[(ty * 8 + i) * 68 + tx * 4] =
                make_float4(s[i][0], s[i][1], s[i][2], s[i][3]);
        __syncthreads();

        #pragma unroll 2
        for (int kk = 0; kk < 64; kk += 4) {
            float rv[4][4];
            *(float4*)&rv[0][0] = *(const float4*)&Vs[(kk + 0) * 68 + tx * 4];
            *(float4*)&rv[1][0] = *(const float4*)&Vs[(kk + 1) * 68 + tx * 4];
            *(float4*)&rv[2][0] = *(const float4*)&Vs[(kk + 2) * 68 + tx * 4];
            *(float4*)&rv[3][0] = *(const float4*)&Vs[(kk + 3) * 68 + tx * 4];
            #pragma unroll
            for (int i = 0; i < 8; i++) {
                float4 rp = *(const float4*)&Ps[(ty * 8 + i) * 68 + kk];
                #pragma unroll
                for (int j = 0; j < 4; j++)
                    o[i][j] += rp.x * rv[0][j] + rp.y * rv[1][j]
                             + rp.z * rv[2][j] + rp.w * rv[3][j];
            }
        }
    }

    #pragma unroll
    for (int i = 0; i < 8; i++) {
        float inv = 1.f / lrow[i];
        int m = q0 + ty * 8 + i;
        *(float4*)(z + rowoff + (size_t)m * DM_ + tx * 4) =
            make_float4(o[i][0] * inv, o[i][1] * inv, o[i][2] * inv, o[i][3] * inv);
    }
}

// ---------------------------------------------------------------------------
extern "C" void kernel_launch(void* const* d_in, const int* in_sizes, int n_in,
                              void* d_out, int out_size)
{
    const float* x  = (const float*)d_in[0];
    const float* cs = (const float*)d_in[1];
    const float* sn = (const float*)d_in[2];
    const float* Wq = (const float*)d_in[3];
    const float* Wk = (const float*)d_in[4];
    const float* Wv = (const float*)d_in[5];
    const float* Wo = (const float*)d_in[6];
    float* out = (float*)d_out;

    float *qp, *kp, *vp, *zp;
    __nv_bfloat16 *ahp, *alp, *bhp, *blp;
    cudaGetSymbolAddress((void**)&qp, g_q);
    cudaGetSymbolAddress((void**)&kp, g_k);
    cudaGetSymbolAddress((void**)&vp, g_v);
    cudaGetSymbolAddress((void**)&zp, g_z);
    cudaGetSymbolAddress((void**)&ahp, g_ah);
    cudaGetSymbolAddress((void**)&alp, g_al);
    cudaGetSymbolAddress((void**)&bhp, g_bh);
    cudaGetSymbolAddress((void**)&blp, g_bl);

    const int GEMM_SMEM = 2 * STG_SZ;   // 61440
    cudaFuncSetAttribute(gemm_mma, cudaFuncAttributeMaxDynamicSharedMemorySize,
                         GEMM_SMEM);

    dim3 tgrid(DM_ / 64, BT_ / 128);         // (16, 32)
    dim3 cgrid(DM_ / 32, DM_ / 32);          // (32, 32)
    dim3 cblk(32, 8);

    // split x once
    conv_split<<<BT_ * DM_ / 1024, 256>>>(x, ahp, alp);

    // Q = x Wq
    conv_T<<<cgrid, cblk>>>(Wq, bhp, blp);
    gemm_mma<<<tgrid, 256, GEMM_SMEM>>>(ahp, alp, bhp, blp, qp);
    // K = x Wk
    conv_T<<<cgrid, cblk>>>(Wk, bhp, blp);
    gemm_mma<<<tgrid, 256, GEMM_SMEM>>>(ahp, alp, bhp, blp, kp);
    // V = x Wv
    conv_T<<<cgrid, cblk>>>(Wv, bhp, blp);
    gemm_mma<<<tgrid, 256, GEMM_SMEM>>>(ahp, alp, bhp, blp, vp);

    rope_qk<<<(BT_ * H_ * 32) / 256, 256>>>(qp, kp, cs, sn);

    const int SMEM = (64 * 132 + 64 * 68 + 64 * 68 + 128 * 68) * 4;
    cudaFuncSetAttribute(attn_kernel,
                         cudaFuncAttributeMaxDynamicSharedMemorySize, SMEM);
    attn_kernel<<<dim3(T_ / 128, B_ * H_), 256, SMEM>>>(qp, kp, vp, zp);

    // out = z Wo
    conv_split<<<BT_ * DM_ / 1024, 256>>>(zp, ahp, alp);
    conv_T<<<cgrid, cblk>>>(Wo, bhp, blp);
    gemm_mma<<<tgrid, 256, GEMM_SMEM>>>(ahp, alp, bhp, blp, out);
}

// round 4
// speedup vs baseline: 2.4691x; 1.6641x over previous
#include <cuda_runtime.h>
#include <cuda_bf16.h>
#include <cstdint>

#define B_   2
#define T_   2048
#define DM_  1024
#define H_   16
#define DH_  64
#define BT_  (B_ * T_)   // 4096

// Scratch (allocation-free rule: device globals)
__device__ float g_q[BT_ * DM_];
__device__ float g_k[BT_ * DM_];
__device__ float g_v[BT_ * DM_];
__device__ __nv_bfloat16 g_ah[BT_ * DM_];   // x hi
__device__ __nv_bfloat16 g_al[BT_ * DM_];   // x lo
__device__ __nv_bfloat16 g_bh[DM_ * DM_];   // W^T hi
__device__ __nv_bfloat16 g_bl[DM_ * DM_];   // W^T lo
__device__ __nv_bfloat16 g_qh[BT_ * DM_], g_ql[BT_ * DM_];
__device__ __nv_bfloat16 g_kh[BT_ * DM_], g_kl[BT_ * DM_];
__device__ __nv_bfloat16 g_vh[BT_ * DM_], g_vl[BT_ * DM_];
__device__ __nv_bfloat16 g_zh[BT_ * DM_], g_zl[BT_ * DM_];

// ===========================================================================
// Warp-MMA helpers (baseline PTX — no tcgen05 on this harness target)
// ===========================================================================
__device__ __forceinline__ uint32_t smem_u32(const void* p) {
    uint32_t a;
    asm("{ .reg .u64 t; cvta.to.shared.u64 t, %1; cvt.u32.u64 %0, t; }"
        : "=r"(a) : "l"(p));
    return a;
}

__device__ __forceinline__ void ldsm4(uint32_t* r, uint32_t addr) {
    asm volatile("ldmatrix.sync.aligned.m8n8.x4.shared.b16 {%0,%1,%2,%3}, [%4];"
                 : "=r"(r[0]), "=r"(r[1]), "=r"(r[2]), "=r"(r[3]) : "r"(addr));
}
__device__ __forceinline__ void ldsm4t(uint32_t* r, uint32_t addr) {
    asm volatile("ldmatrix.sync.aligned.m8n8.x4.trans.shared.b16 {%0,%1,%2,%3}, [%4];"
                 : "=r"(r[0]), "=r"(r[1]), "=r"(r[2]), "=r"(r[3]) : "r"(addr));
}

__device__ __forceinline__ void mma16816(float* c, const uint32_t* a,
                                         const uint32_t* b) {
    asm volatile(
        "mma.sync.aligned.m16n8k16.row.col.f32.bf16.bf16.f32 "
        "{%0,%1,%2,%3}, {%4,%5,%6,%7}, {%8,%9}, {%0,%1,%2,%3};"
        : "+f"(c[0]), "+f"(c[1]), "+f"(c[2]), "+f"(c[3])
        : "r"(a[0]), "r"(a[1]), "r"(a[2]), "r"(a[3]), "r"(b[0]), "r"(b[1]));
}

// split pair (x,y) into bf16 hi/lo packed regs (x -> low half, y -> high half)
__device__ __forceinline__ void split2(float x, float y, uint32_t& hi, uint32_t& lo) {
    __nv_bfloat162 h = __floats2bfloat162_rn(x, y);
    float hx = __bfloat162float(h.x), hy = __bfloat162float(h.y);
    __nv_bfloat162 l = __floats2bfloat162_rn(x - hx, y - hy);
    hi = *(uint32_t*)&h;
    lo = *(uint32_t*)&l;
}

// ===========================================================================
// Conversion kernels
// ===========================================================================
__global__ void conv_split(const float* __restrict__ in,
                           __nv_bfloat16* __restrict__ hi,
                           __nv_bfloat16* __restrict__ lo) {
    int i = (blockIdx.x * 256 + threadIdx.x) * 4;
    float4 v = *(const float4*)(in + i);
    uint32_t h0, l0, h1, l1;
    split2(v.x, v.y, h0, l0);
    split2(v.z, v.w, h1, l1);
    *(uint2*)(hi + i) = make_uint2(h0, h1);
    *(uint2*)(lo + i) = make_uint2(l0, l1);
}

// W [K,N] row-major -> W^T hi/lo [N,K]
__global__ void conv_T(const float* __restrict__ W,
                       __nv_bfloat16* __restrict__ th,
                       __nv_bfloat16* __restrict__ tl) {
    __shared__ float t[32][33];
    const int n0 = blockIdx.x * 32, k0 = blockIdx.y * 32;
    const int tx = threadIdx.x, ty = threadIdx.y;   // (32, 8)
    #pragma unroll
    for (int r = 0; r < 4; r++)
        t[ty * 4 + r][tx] = W[(size_t)(k0 + ty * 4 + r) * DM_ + n0 + tx];
    __syncthreads();
    #pragma unroll
    for (int r = 0; r < 4; r++) {
        float v = t[tx][ty * 4 + r];
        __nv_bfloat16 h = __float2bfloat16(v);
        __nv_bfloat16 l = __float2bfloat16(v - __bfloat162float(h));
        size_t o = (size_t)(n0 + ty * 4 + r) * DM_ + k0 + tx;
        th[o] = h;
        tl[o] = l;
    }
}

// RoPE + scale(q) + hi/lo split for q,k ; plain split for v.
__global__ void rope_split(
    const float* __restrict__ q, const float* __restrict__ k,
    const float* __restrict__ v,
    const float* __restrict__ cs, const float* __restrict__ sn,
    __nv_bfloat16* __restrict__ qh, __nv_bfloat16* __restrict__ ql,
    __nv_bfloat16* __restrict__ kh, __nv_bfloat16* __restrict__ kl,
    __nv_bfloat16* __restrict__ vh, __nv_bfloat16* __restrict__ vl)
{
    int p = blockIdx.x * 256 + threadIdx.x;   // pair index
    int i = p & 31;
    int t = (p >> 9) & (T_ - 1);
    float c = cs[t * 32 + i];
    float s = sn[t * 32 + i];
    size_t e = (size_t)p * 2;
    uint32_t h32, l32;

    float2 qv = *(const float2*)(q + e);
    split2((qv.x * c - qv.y * s) * 0.125f, (qv.x * s + qv.y * c) * 0.125f, h32, l32);
    *(uint32_t*)(qh + e) = h32;  *(uint32_t*)(ql + e) = l32;

    float2 kv = *(const float2*)(k + e);
    split2(kv.x * c - kv.y * s, kv.x * s + kv.y * c, h32, l32);
    *(uint32_t*)(kh + e) = h32;  *(uint32_t*)(kl + e) = l32;

    float2 vv = *(const float2*)(v + e);
    split2(vv.x, vv.y, h32, l32);
    *(uint32_t*)(vh + e) = h32;  *(uint32_t*)(vl + e) = l32;
}

// ===========================================================================
// bf16x2-split GEMM via mma.sync (3 passes): C = A * W  (unchanged from R3)
// ===========================================================================
#define STG_A   10240
#define STG_B   5120
#define STG_SZ  (2*STG_A + 2*STG_B)

__global__ __launch_bounds__(256) void gemm_mma(
    const __nv_bfloat16* __restrict__ Ah, const __nv_bfloat16* __restrict__ Al,
    const __nv_bfloat16* __restrict__ Bh, const __nv_bfloat16* __restrict__ Bl,
    float* __restrict__ C)
{
    extern __shared__ __align__(16) char sm[];
    const int tid  = threadIdx.x;
    const int wid  = tid >> 5;
    const int lane = tid & 31;
    const int wm   = wid & 3;
    const int wn   = wid >> 2;
    const int m0   = blockIdx.y * 128;
    const int n0   = blockIdx.x * 64;
    const uint32_t sbase = smem_u32(sm);

    const __nv_bfloat16* gAh = Ah + (size_t)m0 * DM_;
    const __nv_bfloat16* gAl = Al + (size_t)m0 * DM_;
    const __nv_bfloat16* gBh = Bh + (size_t)n0 * DM_;
    const __nv_bfloat16* gBl = Bl + (size_t)n0 * DM_;

    const int arow = tid >> 2;
    const int acg  = tid & 3;

    const uint32_t a_off = (uint32_t)((lane & 15) * 80 + (lane >> 4) * 16);
    const uint32_t b_off = (uint32_t)((((lane >> 4) * 8) + (lane & 7)) * 80 +
                                      ((lane >> 3) & 1) * 16);

    float acc[2][4][4];
    #pragma unroll
    for (int i = 0; i < 2; i++)
        #pragma unroll
        for (int j = 0; j < 4; j++)
            #pragma unroll
            for (int l = 0; l < 4; l++) acc[i][j][l] = 0.f;

    uint4 ra0, ra1, rl0, rl1, rbh, rbl;

    #define LDG_CHUNK(k0_)                                                    \
        ra0 = *(const uint4*)(gAh + (size_t)arow        * DM_ + (k0_) + acg * 8); \
        ra1 = *(const uint4*)(gAh + (size_t)(arow + 64) * DM_ + (k0_) + acg * 8); \
        rl0 = *(const uint4*)(gAl + (size_t)arow        * DM_ + (k0_) + acg * 8); \
        rl1 = *(const uint4*)(gAl + (size_t)(arow + 64) * DM_ + (k0_) + acg * 8); \
        rbh = *(const uint4*)(gBh + (size_t)arow        * DM_ + (k0_) + acg * 8); \
        rbl = *(const uint4*)(gBl + (size_t)arow        * DM_ + (k0_) + acg * 8);

    #define STS_CHUNK(st_)                                                    \
        {                                                                     \
            char* p = sm + (st_) * STG_SZ;                                    \
            *(uint4*)(p +            arow * 80        + acg * 16) = ra0;      \
            *(uint4*)(p +           (arow + 64) * 80  + acg * 16) = ra1;      \
            *(uint4*)(p + STG_A +    arow * 80        + acg * 16) = rl0;      \
            *(uint4*)(p + STG_A +   (arow + 64) * 80  + acg * 16) = rl1;      \
            *(uint4*)(p + 2*STG_A +  arow * 80        + acg * 16) = rbh;      \
            *(uint4*)(p + 2*STG_A + STG_B + arow * 80 + acg * 16) = rbl;      \
        }

    LDG_CHUNK(0);
    STS_CHUNK(0);
    __syncthreads();

    for (int c = 0; c < DM_ / 32; c++) {
        if (c + 1 < DM_ / 32) { LDG_CHUNK((c + 1) * 32); }

        const uint32_t stb = sbase + (c & 1) * STG_SZ;
        #pragma unroll
        for (int ks = 0; ks < 2; ks++) {
            uint32_t ah[2][4], al[2][4], bh[4][2], bl[4][2];
            #pragma unroll
            for (int mt = 0; mt < 2; mt++) {
                uint32_t ab = stb + (uint32_t)((wm * 32 + mt * 16) * 80 + ks * 32) + a_off;
                ldsm4(ah[mt], ab);
                ldsm4(al[mt], ab + STG_A);
            }
            #pragma unroll
            for (int bt = 0; bt < 2; bt++) {
                uint32_t bb = stb + 2 * STG_A +
                              (uint32_t)((wn * 32 + bt * 16) * 80 + ks * 32) + b_off;
                uint32_t t0[4], t1[4];
                ldsm4(t0, bb);
                ldsm4(t1, bb + STG_B);
                bh[bt*2][0] = t0[0]; bh[bt*2][1] = t0[1];
                bh[bt*2+1][0] = t0[2]; bh[bt*2+1][1] = t0[3];
                bl[bt*2][0] = t1[0]; bl[bt*2][1] = t1[1];
                bl[bt*2+1][0] = t1[2]; bl[bt*2+1][1] = t1[3];
            }
            #pragma unroll
            for (int mt = 0; mt < 2; mt++)
                #pragma unroll
                for (int nt = 0; nt < 4; nt++) {
                    mma16816(acc[mt][nt], ah[mt], bh[nt]);
                    mma16816(acc[mt][nt], ah[mt], bl[nt]);
                    mma16816(acc[mt][nt], al[mt], bh[nt]);
                }
        }

        if (c + 1 < DM_ / 32) {
            __syncthreads();
            STS_CHUNK((c + 1) & 1);
            __syncthreads();
        }
    }

    #pragma unroll
    for (int mt = 0; mt < 2; mt++) {
        int m = m0 + wm * 32 + mt * 16 + (lane >> 2);
        #pragma unroll
        for (int nt = 0; nt < 4; nt++) {
            int n = n0 + wn * 32 + nt * 8 + (lane & 3) * 2;
            *(float2*)(C + (size_t)m * DM_ + n) =
                make_float2(acc[mt][nt][0], acc[mt][nt][1]);
            *(float2*)(C + (size_t)(m + 8) * DM_ + n) =
                make_float2(acc[mt][nt][2], acc[mt][nt][3]);
        }
    }
    #undef LDG_CHUNK
    #undef STS_CHUNK
}

// ===========================================================================
// Tensor-core flash attention (bf16 hi/lo split, causal).
// CTA: 128 q-rows, one (b,h). 8 warps x 16 q-rows. K-tile = 64.
// SMEM pitch 144B (64 bf16 rows + 16B pad) — conflict-free ldmatrix/STS.
// ===========================================================================
#define PIT   144
#define KH_O  0
#define KL_O  9216
#define VH_O  18432
#define VL_O  27648
#define ATT_SMEM 36864

__global__ __launch_bounds__(256) void attn_mma(
    const __nv_bfloat16* __restrict__ qh, const __nv_bfloat16* __restrict__ ql,
    const __nv_bfloat16* __restrict__ kh, const __nv_bfloat16* __restrict__ kl,
    const __nv_bfloat16* __restrict__ vh, const __nv_bfloat16* __restrict__ vl,
    __nv_bfloat16* __restrict__ zh, __nv_bfloat16* __restrict__ zl)
{
    extern __shared__ __align__(16) char sm[];
    const int tid  = threadIdx.x;
    const int lane = tid & 31;
    const int wq   = tid >> 5;            // warp q-subtile (0..7)
    const int qi   = 15 - blockIdx.x;     // heavy tiles first
    const int bh_  = blockIdx.y;
    const int b    = bh_ >> 4;
    const int h    = bh_ & 15;
    const int q0   = qi * 128;
    const uint32_t sb = smem_u32(sm);
    const size_t hcol = (size_t)h * DH_;

    // ---- stage Q (hi/lo) through smem, extract A-fragments ----
    {
        int r = tid >> 3, c = tid & 7;
        #pragma unroll
        for (int i = 0; i < 4; i++) {
            int row = r + i * 32;
            size_t g = ((size_t)(b * T_ + q0 + row)) * DM_ + hcol + c * 8;
            *(uint4*)(sm + row * PIT + c * 16)         = *(const uint4*)(qh + g);
            *(uint4*)(sm + 18432 + row * PIT + c * 16) = *(const uint4*)(ql + g);
        }
    }
    __syncthreads();

    uint32_t qfh[4][4], qfl[4][4];
    {
        const uint32_t a_off = (lane & 15) * PIT + (lane >> 4) * 16;
        #pragma unroll
        for (int ks = 0; ks < 4; ks++) {
            ldsm4(qfh[ks], sb + (wq * 16) * PIT + ks * 32 + a_off);
            ldsm4(qfl[ks], sb + 18432 + (wq * 16) * PIT + ks * 32 + a_off);
        }
    }
    __syncthreads();   // Q region now reusable for K/V

    float o[8][4];
    #pragma unroll
    for (int i = 0; i < 8; i++)
        #pragma unroll
        for (int j = 0; j < 4; j++) o[i][j] = 0.f;
    float m_lo = -1e30f, m_hi = -1e30f, l_lo = 0.f, l_hi = 0.f;

    const int nkt = 2 * qi + 2;
    const uint32_t k_off = ((lane >> 4) * 8 + (lane & 7)) * PIT + ((lane >> 3) & 1) * 16;
    const uint32_t v_off = (lane & 7) * PIT + ((lane >> 3) & 1) * 8 * PIT + (lane >> 4) * 16;
    const int qg_lo = q0 + wq * 16 + (lane >> 2);
    const int qg_hi = qg_lo + 8;

    for (int kt = 0; kt < nkt; kt++) {
        const int k0 = kt * 64;
        if (kt) __syncthreads();    // previous iter's smem reads done

        // load K/V hi/lo tiles [64 x 64]
        {
            int r = tid >> 3, c = tid & 7;
            #pragma unroll
            for (int i = 0; i < 2; i++) {
                int row = r + i * 32;
                size_t g = ((size_t)(b * T_ + k0 + row)) * DM_ + hcol + c * 8;
                *(uint4*)(sm + KH_O + row * PIT + c * 16) = *(const uint4*)(kh + g);
                *(uint4*)(sm + KL_O + row * PIT + c * 16) = *(const uint4*)(kl + g);
                *(uint4*)(sm + VH_O + row * PIT + c * 16) = *(const uint4*)(vh + g);
                *(uint4*)(sm + VL_O + row * PIT + c * 16) = *(const uint4*)(vl + g);
            }
        }
        __syncthreads();

        // ---- S = Q K^T (3-pass split) ----
        float sf[8][4];
        #pragma unroll
        for (int i = 0; i < 8; i++)
            #pragma unroll
            for (int j = 0; j < 4; j++) sf[i][j] = 0.f;

        #pragma unroll
        for (int ks = 0; ks < 4; ks++) {
            #pragma unroll
            for (int nt2 = 0; nt2 < 4; nt2++) {
                uint32_t th[4], tl[4];
                ldsm4(th, sb + KH_O + (nt2 * 16) * PIT + ks * 32 + k_off);
                ldsm4(tl, sb + KL_O + (nt2 * 16) * PIT + ks * 32 + k_off);
                mma16816(sf[2*nt2],   qfh[ks], th);
                mma16816(sf[2*nt2],   qfh[ks], tl);
                mma16816(sf[2*nt2],   qfl[ks], th);
                mma16816(sf[2*nt2+1], qfh[ks], th + 2);
                mma16816(sf[2*nt2+1], qfh[ks], tl + 2);
                mma16816(sf[2*nt2+1], qfl[ks], th + 2);
            }
        }

        // causal mask (only diagonal-overlapping tiles)
        if (kt >= nkt - 2) {
            #pragma unroll
            for (int nt = 0; nt < 8; nt++) {
                int kg = k0 + nt * 8 + (lane & 3) * 2;
                if (kg     > qg_lo) sf[nt][0] = -1e30f;
                if (kg + 1 > qg_lo) sf[nt][1] = -1e30f;
                if (kg     > qg_hi) sf[nt][2] = -1e30f;
                if (kg + 1 > qg_hi) sf[nt][3] = -1e30f;
            }
        }

        // ---- online softmax ----
        float mx_lo = sf[0][0], mx_hi = sf[0][2];
        #pragma unroll
        for (int nt = 0; nt < 8; nt++) {
            mx_lo = fmaxf(mx_lo, fmaxf(sf[nt][0], sf[nt][1]));
            mx_hi = fmaxf(mx_hi, fmaxf(sf[nt][2], sf[nt][3]));
        }
        mx_lo = fmaxf(mx_lo, __shfl_xor_sync(0xffffffffu, mx_lo, 1));
        mx_lo = fmaxf(mx_lo, __shfl_xor_sync(0xffffffffu, mx_lo, 2));
        mx_hi = fmaxf(mx_hi, __shfl_xor_sync(0xffffffffu, mx_hi, 1));
        mx_hi = fmaxf(mx_hi, __shfl_xor_sync(0xffffffffu, mx_hi, 2));

        float nm_lo = fmaxf(m_lo, mx_lo), nm_hi = fmaxf(m_hi, mx_hi);
        float cr_lo = __expf(m_lo - nm_lo), cr_hi = __expf(m_hi - nm_hi);
        m_lo = nm_lo; m_hi = nm_hi;

        float rs_lo = 0.f, rs_hi = 0.f;
        #pragma unroll
        for (int nt = 0; nt < 8; nt++) {
            sf[nt][0] = __expf(sf[nt][0] - nm_lo); rs_lo += sf[nt][0];
            sf[nt][1] = __expf(sf[nt][1] - nm_lo); rs_lo += sf[nt][1];
            sf[nt][2] = __expf(sf[nt][2] - nm_hi); rs_hi += sf[nt][2];
            sf[nt][3] = __expf(sf[nt][3] - nm_hi); rs_hi += sf[nt][3];
        }
        rs_lo += __shfl_xor_sync(0xffffffffu, rs_lo, 1);
        rs_lo += __shfl_xor_sync(0xffffffffu, rs_lo, 2);
        rs_hi += __shfl_xor_sync(0xffffffffu, rs_hi, 1);
        rs_hi += __shfl_xor_sync(0xffffffffu, rs_hi, 2);
        l_lo = l_lo * cr_lo + rs_lo;
        l_hi = l_hi * cr_hi + rs_hi;

        #pragma unroll
        for (int nt = 0; nt < 8; nt++) {
            o[nt][0] *= cr_lo; o[nt][1] *= cr_lo;
            o[nt][2] *= cr_hi; o[nt][3] *= cr_hi;
        }

        // ---- pack P (fp32 frags -> bf16 hi/lo A-operands), in registers ----
        uint32_t pfh[4][4], pfl[4][4];
        #pragma unroll
        for (int j = 0; j < 4; j++) {
            split2(sf[2*j][0],   sf[2*j][1],   pfh[j][0], pfl[j][0]);
            split2(sf[2*j][2],   sf[2*j][3],   pfh[j][1], pfl[j][1]);
            split2(sf[2*j+1][0], sf[2*j+1][1], pfh[j][2], pfl[j][2]);
            split2(sf[2*j+1][2], sf[2*j+1][3], pfh[j][3], pfl[j][3]);
        }

        // ---- O += P V (3-pass split, V via ldmatrix.trans) ----
        #pragma unroll
        for (int j = 0; j < 4; j++) {
            #pragma unroll
            for (int d2 = 0; d2 < 4; d2++) {
                uint32_t th[4], tl[4];
                ldsm4t(th, sb + VH_O + (j * 16) * PIT + d2 * 32 + v_off);
                ldsm4t(tl, sb + VL_O + (j * 16) * PIT + d2 * 32 + v_off);
                mma16816(o[2*d2],   pfh[j], th);
                mma16816(o[2*d2],   pfh[j], tl);
                mma16816(o[2*d2],   pfl[j], th);
                mma16816(o[2*d2+1], pfh[j], th + 2);
                mma16816(o[2*d2+1], pfh[j], tl + 2);
                mma16816(o[2*d2+1], pfl[j], th + 2);
            }
        }
    }

    // ---- epilogue: normalize, split, write zh/zl ----
    float il_lo = 1.f / l_lo, il_hi = 1.f / l_hi;
    size_t out_lo = ((size_t)(b * T_ + qg_lo)) * DM_ + hcol + (lane & 3) * 2;
    #pragma unroll
    for (int nt = 0; nt < 8; nt++) {
        uint32_t h32, l32;
        split2(o[nt][0] * il_lo, o[nt][1] * il_lo, h32, l32);
        *(uint32_t*)(zh + out_lo + nt * 8) = h32;
        *(uint32_t*)(zl + out_lo + nt * 8) = l32;
        split2(o[nt][2] * il_hi, o[nt][3] * il_hi, h32, l32);
        *(uint32_t*)(zh + out_lo + 8 * DM_ + nt * 8) = h32;
        *(uint32_t*)(zl + out_lo + 8 * DM_ + nt * 8) = l32;
    }
}

// ---------------------------------------------------------------------------
extern "C" void kernel_launch(void* const* d_in, const int* in_sizes, int n_in,
                              void* d_out, int out_size)
{
    const float* x  = (const float*)d_in[0];
    const float* cs = (const float*)d_in[1];
    const float* sn = (const float*)d_in[2];
    const float* Wq = (const float*)d_in[3];
    const float* Wk = (const float*)d_in[4];
    const float* Wv = (const float*)d_in[5];
    const float* Wo = (const float*)d_in[6];
    float* out = (float*)d_out;

    float *qp, *kp, *vp;
    __nv_bfloat16 *ahp, *alp, *bhp, *blp;
    __nv_bfloat16 *qhp, *qlp, *khp, *klp, *vhp, *vlp, *zhp, *zlp;
    cudaGetSymbolAddress((void**)&qp, g_q);
    cudaGetSymbolAddress((void**)&kp, g_k);
    cudaGetSymbolAddress((void**)&vp, g_v);
    cudaGetSymbolAddress((void**)&ahp, g_ah);
    cudaGetSymbolAddress((void**)&alp, g_al);
    cudaGetSymbolAddress((void**)&bhp, g_bh);
    cudaGetSymbolAddress((void**)&blp, g_bl);
    cudaGetSymbolAddress((void**)&qhp, g_qh);
    cudaGetSymbolAddress((void**)&qlp, g_ql);
    cudaGetSymbolAddress((void**)&khp, g_kh);
    cudaGetSymbolAddress((void**)&klp, g_kl);
    cudaGetSymbolAddress((void**)&vhp, g_vh);
    cudaGetSymbolAddress((void**)&vlp, g_vl);
    cudaGetSymbolAddress((void**)&zhp, g_zh);
    cudaGetSymbolAddress((void**)&zlp, g_zl);

    const int GEMM_SMEM = 2 * STG_SZ;
    cudaFuncSetAttribute(gemm_mma, cudaFuncAttributeMaxDynamicSharedMemorySize,
                         GEMM_SMEM);

    dim3 tgrid(DM_ / 64, BT_ / 128);         // (16, 32)
    dim3 cgrid(DM_ / 32, DM_ / 32);
    dim3 cblk(32, 8);

    conv_split<<<BT_ * DM_ / 1024, 256>>>(x, ahp, alp);

    conv_T<<<cgrid, cblk>>>(Wq, bhp, blp);
    gemm_mma<<<tgrid, 256, GEMM_SMEM>>>(ahp, alp, bhp, blp, qp);
    conv_T<<<cgrid, cblk>>>(Wk, bhp, blp);
    gemm_mma<<<tgrid, 256, GEMM_SMEM>>>(ahp, alp, bhp, blp, kp);
    conv_T<<<cgrid, cblk>>>(Wv, bhp, blp);
    gemm_mma<<<tgrid, 256, GEMM_SMEM>>>(ahp, alp, bhp, blp, vp);

    rope_split<<<BT_ * DM_ / 512, 256>>>(qp, kp, vp, cs, sn,
                                         qhp, qlp, khp, klp, vhp, vlp);

    attn_mma<<<dim3(16, B_ * H_), 256, ATT_SMEM>>>(qhp, qlp, khp, klp,
                                                   vhp, vlp, zhp, zlp);

    conv_T<<<cgrid, cblk>>>(Wo, bhp, blp);
    gemm_mma<<<tgrid, 256, GEMM_SMEM>>>(zhp, zlp, bhp, blp, out);
}

// round 5
// speedup vs baseline: 2.5560x; 1.0352x over previous
#include <cuda_runtime.h>
#include <cuda_bf16.h>
#include <cstdint>

#define B_   2
#define T_   2048
#define DM_  1024
#define H_   16
#define DH_  64
#define BT_  (B_ * T_)   // 4096

// Scratch (allocation-free rule: device globals)
__device__ float g_q[BT_ * DM_];
__device__ float g_k[BT_ * DM_];
__device__ float g_v[BT_ * DM_];
__device__ __nv_bfloat16 g_ah[BT_ * DM_];          // x hi
__device__ __nv_bfloat16 g_al[BT_ * DM_];          // x lo
__device__ __nv_bfloat16 g_wth[3 * DM_ * DM_];     // W^T hi (qkv stacked / out)
__device__ __nv_bfloat16 g_wtl[3 * DM_ * DM_];     // W^T lo
__device__ __nv_bfloat16 g_qh[BT_ * DM_], g_ql[BT_ * DM_];
__device__ __nv_bfloat16 g_kh[BT_ * DM_], g_kl[BT_ * DM_];
__device__ __nv_bfloat16 g_vh[BT_ * DM_], g_vl[BT_ * DM_];
__device__ __nv_bfloat16 g_zh[BT_ * DM_], g_zl[BT_ * DM_];

// ===========================================================================
// Warp-MMA + cp.async helpers (baseline PTX — no tcgen05 on this harness)
// ===========================================================================
__device__ __forceinline__ uint32_t smem_u32(const void* p) {
    uint32_t a;
    asm("{ .reg .u64 t; cvta.to.shared.u64 t, %1; cvt.u32.u64 %0, t; }"
        : "=r"(a) : "l"(p));
    return a;
}

__device__ __forceinline__ void ldsm4(uint32_t* r, uint32_t addr) {
    asm volatile("ldmatrix.sync.aligned.m8n8.x4.shared.b16 {%0,%1,%2,%3}, [%4];"
                 : "=r"(r[0]), "=r"(r[1]), "=r"(r[2]), "=r"(r[3]) : "r"(addr));
}
__device__ __forceinline__ void ldsm4t(uint32_t* r, uint32_t addr) {
    asm volatile("ldmatrix.sync.aligned.m8n8.x4.trans.shared.b16 {%0,%1,%2,%3}, [%4];"
                 : "=r"(r[0]), "=r"(r[1]), "=r"(r[2]), "=r"(r[3]) : "r"(addr));
}

__device__ __forceinline__ void mma16816(float* c, const uint32_t* a,
                                         const uint32_t* b) {
    asm volatile(
        "mma.sync.aligned.m16n8k16.row.col.f32.bf16.bf16.f32 "
        "{%0,%1,%2,%3}, {%4,%5,%6,%7}, {%8,%9}, {%0,%1,%2,%3};"
        : "+f"(c[0]), "+f"(c[1]), "+f"(c[2]), "+f"(c[3])
        : "r"(a[0]), "r"(a[1]), "r"(a[2]), "r"(a[3]), "r"(b[0]), "r"(b[1]));
}

#define CP_ASYNC16(dst, src) \
    asm volatile("cp.async.cg.shared.global [%0], [%1], 16;" :: "r"(dst), "l"(src))
#define CP_COMMIT() asm volatile("cp.async.commit_group;")
#define CP_WAIT1()  asm volatile("cp.async.wait_group 1;")

// split pair (x,y) into bf16 hi/lo packed regs
__device__ __forceinline__ void split2(float x, float y, uint32_t& hi, uint32_t& lo) {
    __nv_bfloat162 h = __floats2bfloat162_rn(x, y);
    float hx = __bfloat162float(h.x), hy = __bfloat162float(h.y);
    __nv_bfloat162 l = __floats2bfloat162_rn(x - hx, y - hy);
    hi = *(uint32_t*)&h;
    lo = *(uint32_t*)&l;
}

// ===========================================================================
// Conversion kernels
// ===========================================================================
__global__ void conv_split(const float* __restrict__ in,
                           __nv_bfloat16* __restrict__ hi,
                           __nv_bfloat16* __restrict__ lo) {
    int i = (blockIdx.x * 256 + threadIdx.x) * 4;
    float4 v = *(const float4*)(in + i);
    uint32_t h0, l0, h1, l1;
    split2(v.x, v.y, h0, l0);
    split2(v.z, v.w, h1, l1);
    *(uint2*)(hi + i) = make_uint2(h0, h1);
    *(uint2*)(lo + i) = make_uint2(l0, l1);
}

// W [K,N] row-major -> W^T hi/lo [N,K]
__global__ void conv_T(const float* __restrict__ W,
                       __nv_bfloat16* __restrict__ th,
                       __nv_bfloat16* __restrict__ tl) {
    __shared__ float t[32][33];
    const int n0 = blockIdx.x * 32, k0 = blockIdx.y * 32;
    const int tx = threadIdx.x, ty = threadIdx.y;   // (32, 8)
    #pragma unroll
    for (int r = 0; r < 4; r++)
        t[ty * 4 + r][tx] = W[(size_t)(k0 + ty * 4 + r) * DM_ + n0 + tx];
    __syncthreads();
    #pragma unroll
    for (int r = 0; r < 4; r++) {
        float v = t[tx][ty * 4 + r];
        __nv_bfloat16 h = __float2bfloat16(v);
        __nv_bfloat16 l = __float2bfloat16(v - __bfloat162float(h));
        size_t o = (size_t)(n0 + ty * 4 + r) * DM_ + k0 + tx;
        th[o] = h;
        tl[o] = l;
    }
}

// RoPE + scale(q) + hi/lo split for q,k ; plain split for v.
__global__ void rope_split(
    const float* __restrict__ q, const float* __restrict__ k,
    const float* __restrict__ v,
    const float* __restrict__ cs, const float* __restrict__ sn,
    __nv_bfloat16* __restrict__ qh, __nv_bfloat16* __restrict__ ql,
    __nv_bfloat16* __restrict__ kh, __nv_bfloat16* __restrict__ kl,
    __nv_bfloat16* __restrict__ vh, __nv_bfloat16* __restrict__ vl)
{
    int p = blockIdx.x * 256 + threadIdx.x;   // pair index
    int i = p & 31;
    int t = (p >> 9) & (T_ - 1);
    float c = cs[t * 32 + i];
    float s = sn[t * 32 + i];
    size_t e = (size_t)p * 2;
    uint32_t h32, l32;

    float2 qv = *(const float2*)(q + e);
    split2((qv.x * c - qv.y * s) * 0.125f, (qv.x * s + qv.y * c) * 0.125f, h32, l32);
    *(uint32_t*)(qh + e) = h32;  *(uint32_t*)(ql + e) = l32;

    float2 kv = *(const float2*)(k + e);
    split2(kv.x * c - kv.y * s, kv.x * s + kv.y * c, h32, l32);
    *(uint32_t*)(kh + e) = h32;  *(uint32_t*)(kl + e) = l32;

    float2 vv = *(const float2*)(v + e);
    split2(vv.x, vv.y, h32, l32);
    *(uint32_t*)(vh + e) = h32;  *(uint32_t*)(vl + e) = l32;
}

// ===========================================================================
// bf16x2-split GEMM, 128x128 tile, BK=32, cp.async 3-stage, 1 sync/iter.
//   blockIdx.x: [0, 8*nw) ; widx = x>>3 selects weight slab + output buffer.
//   8 warps (4 m x 2 n), warp tile 32x64. SMEM pitch 80B.
// ===========================================================================
#define GP      80                    // smem row pitch (32 bf16 + 16B pad)
#define TSZ     (128 * GP)            // one operand tile: 10240 B
#define STG     (4 * TSZ)             // stage: Ah,Al,Bh,Bl = 40960 B
#define G_SMEM  (3 * STG)             // 122880 B

__global__ __launch_bounds__(256) void gemm128(
    const __nv_bfloat16* __restrict__ Ah, const __nv_bfloat16* __restrict__ Al,
    const __nv_bfloat16* __restrict__ Bh, const __nv_bfloat16* __restrict__ Bl,
    float* __restrict__ C0, float* __restrict__ C1, float* __restrict__ C2)
{
    extern __shared__ __align__(16) char sm[];
    const int tid  = threadIdx.x;
    const int wid  = tid >> 5;
    const int lane = tid & 31;
    const int wm   = wid & 3;
    const int wn   = wid >> 2;
    const int widx = blockIdx.x >> 3;
    const int n0   = (blockIdx.x & 7) * 128;
    const int m0   = blockIdx.y * 128;
    const uint32_t sb = smem_u32(sm);

    float* C = (widx == 0) ? C0 : (widx == 1) ? C1 : C2;
    const __nv_bfloat16* src[4] = {
        Ah + (size_t)m0 * DM_, Al + (size_t)m0 * DM_,
        Bh + (size_t)widx * DM_ * DM_ + (size_t)n0 * DM_,
        Bl + (size_t)widx * DM_ * DM_ + (size_t)n0 * DM_ };

    const int row = tid >> 2;          // 0..63
    const int cg  = tid & 3;           // 16B chunk in BK row

    // issue one stage of cp.async (8 chunks/thread)
    #define ISSUE(st_, k0_)                                                    \
        {                                                                      \
            uint32_t d0 = sb + (st_) * STG + row * GP + cg * 16;               \
            _Pragma("unroll")                                                  \
            for (int t = 0; t < 4; t++) {                                      \
                const __nv_bfloat16* g = src[t] + (size_t)row * DM_ + (k0_) + cg * 8; \
                CP_ASYNC16(d0 + t * TSZ,           g);                         \
                CP_ASYNC16(d0 + t * TSZ + 64 * GP, g + (size_t)64 * DM_);      \
            }                                                                  \
            CP_COMMIT();                                                       \
        }

    const uint32_t a_off = (uint32_t)((lane & 15) * GP + (lane >> 4) * 16);
    const uint32_t b_off = (uint32_t)((((lane >> 4) * 8) + (lane & 7)) * GP +
                                      ((lane >> 3) & 1) * 16);

    float acc[2][8][4];
    #pragma unroll
    for (int i = 0; i < 2; i++)
        #pragma unroll
        for (int j = 0; j < 8; j++)
            #pragma unroll
            for (int l = 0; l < 4; l++) acc[i][j][l] = 0.f;

    ISSUE(0, 0);
    ISSUE(1, 32);

    const int NIT = DM_ / 32;   // 32
    for (int c = 0; c < NIT; c++) {
        CP_WAIT1();
        __syncthreads();

        if (c + 2 < NIT) { ISSUE((c + 2) % 3, (c + 2) * 32); }
        else             { CP_COMMIT(); }

        const uint32_t stb = sb + (c % 3) * STG;
        #pragma unroll
        for (int ks = 0; ks < 2; ks++) {
            uint32_t ahf[2][4], alf[2][4];
            #pragma unroll
            for (int mt = 0; mt < 2; mt++) {
                uint32_t ab = stb + (uint32_t)((wm * 32 + mt * 16) * GP + ks * 32) + a_off;
                ldsm4(ahf[mt], ab);
                ldsm4(alf[mt], ab + TSZ);
            }
            #pragma unroll
            for (int nt = 0; nt < 4; nt++) {       // 16 n-rows each
                uint32_t bb = stb + 2 * TSZ +
                              (uint32_t)((wn * 64 + nt * 16) * GP + ks * 32) + b_off;
                uint32_t th[4], tl[4];
                ldsm4(th, bb);
                ldsm4(tl, bb + TSZ);
                #pragma unroll
                for (int mt = 0; mt < 2; mt++) {
                    mma16816(acc[mt][2*nt],   ahf[mt], th);
                    mma16816(acc[mt][2*nt],   ahf[mt], tl);
                    mma16816(acc[mt][2*nt],   alf[mt], th);
                    mma16816(acc[mt][2*nt+1], ahf[mt], th + 2);
                    mma16816(acc[mt][2*nt+1], ahf[mt], tl + 2);
                    mma16816(acc[mt][2*nt+1], alf[mt], th + 2);
                }
            }
        }
    }

    // epilogue
    #pragma unroll
    for (int mt = 0; mt < 2; mt++) {
        int m = m0 + wm * 32 + mt * 16 + (lane >> 2);
        #pragma unroll
        for (int nt = 0; nt < 8; nt++) {
            int n = n0 + wn * 64 + nt * 8 + (lane & 3) * 2;
            *(float2*)(C + (size_t)m * DM_ + n) =
                make_float2(acc[mt][nt][0], acc[mt][nt][1]);
            *(float2*)(C + (size_t)(m + 8) * DM_ + n) =
                make_float2(acc[mt][nt][2], acc[mt][nt][3]);
        }
    }
    #undef ISSUE
}

// ===========================================================================
// Tensor-core flash attention (bf16 hi/lo split, causal) — unchanged from R4.
// ===========================================================================
#define PIT   144
#define KH_O  0
#define KL_O  9216
#define VH_O  18432
#define VL_O  27648
#define ATT_SMEM 36864

__global__ __launch_bounds__(256) void attn_mma(
    const __nv_bfloat16* __restrict__ qh, const __nv_bfloat16* __restrict__ ql,
    const __nv_bfloat16* __restrict__ kh, const __nv_bfloat16* __restrict__ kl,
    const __nv_bfloat16* __restrict__ vh, const __nv_bfloat16* __restrict__ vl,
    __nv_bfloat16* __restrict__ zh, __nv_bfloat16* __restrict__ zl)
{
    extern __shared__ __align__(16) char sm[];
    const int tid  = threadIdx.x;
    const int lane = tid & 31;
    const int wq   = tid >> 5;
    const int qi   = 15 - blockIdx.x;
    const int bh_  = blockIdx.y;
    const int b    = bh_ >> 4;
    const int h    = bh_ & 15;
    const int q0   = qi * 128;
    const uint32_t sb = smem_u32(sm);
    const size_t hcol = (size_t)h * DH_;

    {
        int r = tid >> 3, c = tid & 7;
        #pragma unroll
        for (int i = 0; i < 4; i++) {
            int row = r + i * 32;
            size_t g = ((size_t)(b * T_ + q0 + row)) * DM_ + hcol + c * 8;
            *(uint4*)(sm + row * PIT + c * 16)         = *(const uint4*)(qh + g);
            *(uint4*)(sm + 18432 + row * PIT + c * 16) = *(const uint4*)(ql + g);
        }
    }
    __syncthreads();

    uint32_t qfh[4][4], qfl[4][4];
    {
        const uint32_t a_off = (lane & 15) * PIT + (lane >> 4) * 16;
        #pragma unroll
        for (int ks = 0; ks < 4; ks++) {
            ldsm4(qfh[ks], sb + (wq * 16) * PIT + ks * 32 + a_off);
            ldsm4(qfl[ks], sb + 18432 + (wq * 16) * PIT + ks * 32 + a_off);
        }
    }
    __syncthreads();

    float o[8][4];
    #pragma unroll
    for (int i = 0; i < 8; i++)
        #pragma unroll
        for (int j = 0; j < 4; j++) o[i][j] = 0.f;
    float m_lo = -1e30f, m_hi = -1e30f, l_lo = 0.f, l_hi = 0.f;

    const int nkt = 2 * qi + 2;
    const uint32_t k_off = ((lane >> 4) * 8 + (lane & 7)) * PIT + ((lane >> 3) & 1) * 16;
    const uint32_t v_off = (lane & 7) * PIT + ((lane >> 3) & 1) * 8 * PIT + (lane >> 4) * 16;
    const int qg_lo = q0 + wq * 16 + (lane >> 2);
    const int qg_hi = qg_lo + 8;

    for (int kt = 0; kt < nkt; kt++) {
        const int k0 = kt * 64;
        if (kt) __syncthreads();

        {
            int r = tid >> 3, c = tid & 7;
            #pragma unroll
            for (int i = 0; i < 2; i++) {
                int row = r + i * 32;
                size_t g = ((size_t)(b * T_ + k0 + row)) * DM_ + hcol + c * 8;
                *(uint4*)(sm + KH_O + row * PIT + c * 16) = *(const uint4*)(kh + g);
                *(uint4*)(sm + KL_O + row * PIT + c * 16) = *(const uint4*)(kl + g);
                *(uint4*)(sm + VH_O + row * PIT + c * 16) = *(const uint4*)(vh + g);
                *(uint4*)(sm + VL_O + row * PIT + c * 16) = *(const uint4*)(vl + g);
            }
        }
        __syncthreads();

        float sf[8][4];
        #pragma unroll
        for (int i = 0; i < 8; i++)
            #pragma unroll
            for (int j = 0; j < 4; j++) sf[i][j] = 0.f;

        #pragma unroll
        for (int ks = 0; ks < 4; ks++) {
            #pragma unroll
            for (int nt2 = 0; nt2 < 4; nt2++) {
                uint32_t th[4], tl[4];
                ldsm4(th, sb + KH_O + (nt2 * 16) * PIT + ks * 32 + k_off);
                ldsm4(tl, sb + KL_O + (nt2 * 16) * PIT + ks * 32 + k_off);
                mma16816(sf[2*nt2],   qfh[ks], th);
                mma16816(sf[2*nt2],   qfh[ks], tl);
                mma16816(sf[2*nt2],   qfl[ks], th);
                mma16816(sf[2*nt2+1], qfh[ks], th + 2);
                mma16816(sf[2*nt2+1], qfh[ks], tl + 2);
                mma16816(sf[2*nt2+1], qfl[ks], th + 2);
            }
        }

        if (kt >= nkt - 2) {
            #pragma unroll
            for (int nt = 0; nt < 8; nt++) {
                int kg = k0 + nt * 8 + (lane & 3) * 2;
                if (kg     > qg_lo) sf[nt][0] = -1e30f;
                if (kg + 1 > qg_lo) sf[nt][1] = -1e30f;
                if (kg     > qg_hi) sf[nt][2] = -1e30f;
                if (kg + 1 > qg_hi) sf[nt][3] = -1e30f;
            }
        }

        float mx_lo = sf[0][0], mx_hi = sf[0][2];
        #pragma unroll
        for (int nt = 0; nt < 8; nt++) {
            mx_lo = fmaxf(mx_lo, fmaxf(sf[nt][0], sf[nt][1]));
            mx_hi = fmaxf(mx_hi, fmaxf(sf[nt][2], sf[nt][3]));
        }
        mx_lo = fmaxf(mx_lo, __shfl_xor_sync(0xffffffffu, mx_lo, 1));
        mx_lo = fmaxf(mx_lo, __shfl_xor_sync(0xffffffffu, mx_lo, 2));
        mx_hi = fmaxf(mx_hi, __shfl_xor_sync(0xffffffffu, mx_hi, 1));
        mx_hi = fmaxf(mx_hi, __shfl_xor_sync(0xffffffffu, mx_hi, 2));

        float nm_lo = fmaxf(m_lo, mx_lo), nm_hi = fmaxf(m_hi, mx_hi);
        float cr_lo = __expf(m_lo - nm_lo), cr_hi = __expf(m_hi - nm_hi);
        m_lo = nm_lo; m_hi = nm_hi;

        float rs_lo = 0.f, rs_hi = 0.f;
        #pragma unroll
        for (int nt = 0; nt < 8; nt++) {
            sf[nt][0] = __expf(sf[nt][0] - nm_lo); rs_lo += sf[nt][0];
            sf[nt][1] = __expf(sf[nt][1] - nm_lo); rs_lo += sf[nt][1];
            sf[nt][2] = __expf(sf[nt][2] - nm_hi); rs_hi += sf[nt][2];
            sf[nt][3] = __expf(sf[nt][3] - nm_hi); rs_hi += sf[nt][3];
        }
        rs_lo += __shfl_xor_sync(0xffffffffu, rs_lo, 1);
        rs_lo += __shfl_xor_sync(0xffffffffu, rs_lo, 2);
        rs_hi += __shfl_xor_sync(0xffffffffu, rs_hi, 1);
        rs_hi += __shfl_xor_sync(0xffffffffu, rs_hi, 2);
        l_lo = l_lo * cr_lo + rs_lo;
        l_hi = l_hi * cr_hi + rs_hi;

        #pragma unroll
        for (int nt = 0; nt < 8; nt++) {
            o[nt][0] *= cr_lo; o[nt][1] *= cr_lo;
            o[nt][2] *= cr_hi; o[nt][3] *= cr_hi;
        }

        uint32_t pfh[4][4], pfl[4][4];
        #pragma unroll
        for (int j = 0; j < 4; j++) {
            split2(sf[2*j][0],   sf[2*j][1],   pfh[j][0], pfl[j][0]);
            split2(sf[2*j][2],   sf[2*j][3],   pfh[j][1], pfl[j][1]);
            split2(sf[2*j+1][0], sf[2*j+1][1], pfh[j][2], pfl[j][2]);
            split2(sf[2*j+1][2], sf[2*j+1][3], pfh[j][3], pfl[j][3]);
        }

        #pragma unroll
        for (int j = 0; j < 4; j++) {
            #pragma unroll
            for (int d2 = 0; d2 < 4; d2++) {
                uint32_t th[4], tl[4];
                ldsm4t(th, sb + VH_O + (j * 16) * PIT + d2 * 32 + v_off);
                ldsm4t(tl, sb + VL_O + (j * 16) * PIT + d2 * 32 + v_off);
                mma16816(o[2*d2],   pfh[j], th);
                mma16816(o[2*d2],   pfh[j], tl);
                mma16816(o[2*d2],   pfl[j], th);
                mma16816(o[2*d2+1], pfh[j], th + 2);
                mma16816(o[2*d2+1], pfh[j], tl + 2);
                mma16816(o[2*d2+1], pfl[j], th + 2);
            }
        }
    }

    float il_lo = 1.f / l_lo, il_hi = 1.f / l_hi;
    size_t out_lo = ((size_t)(b * T_ + qg_lo)) * DM_ + hcol + (lane & 3) * 2;
    #pragma unroll
    for (int nt = 0; nt < 8; nt++) {
        uint32_t h32, l32;
        split2(o[nt][0] * il_lo, o[nt][1] * il_lo, h32, l32);
        *(uint32_t*)(zh + out_lo + nt * 8) = h32;
        *(uint32_t*)(zl + out_lo + nt * 8) = l32;
        split2(o[nt][2] * il_hi, o[nt][3] * il_hi, h32, l32);
        *(uint32_t*)(zh + out_lo + 8 * DM_ + nt * 8) = h32;
        *(uint32_t*)(zl + out_lo + 8 * DM_ + nt * 8) = l32;
    }
}

// ---------------------------------------------------------------------------
extern "C" void kernel_launch(void* const* d_in, const int* in_sizes, int n_in,
                              void* d_out, int out_size)
{
    const float* x  = (const float*)d_in[0];
    const float* cs = (const float*)d_in[1];
    const float* sn = (const float*)d_in[2];
    const float* Wq = (const float*)d_in[3];
    const float* Wk = (const float*)d_in[4];
    const float* Wv = (const float*)d_in[5];
    const float* Wo = (const float*)d_in[6];
    float* out = (float*)d_out;

    float *qp, *kp, *vp;
    __nv_bfloat16 *ahp, *alp, *wth, *wtl;
    __nv_bfloat16 *qhp, *qlp, *khp, *klp, *vhp, *vlp, *zhp, *zlp;
    cudaGetSymbolAddress((void**)&qp, g_q);
    cudaGetSymbolAddress((void**)&kp, g_k);
    cudaGetSymbolAddress((void**)&vp, g_v);
    cudaGetSymbolAddress((void**)&ahp, g_ah);
    cudaGetSymbolAddress((void**)&alp, g_al);
    cudaGetSymbolAddress((void**)&wth, g_wth);
    cudaGetSymbolAddress((void**)&wtl, g_wtl);
    cudaGetSymbolAddress((void**)&qhp, g_qh);
    cudaGetSymbolAddress((void**)&qlp, g_ql);
    cudaGetSymbolAddress((void**)&khp, g_kh);
    cudaGetSymbolAddress((void**)&klp, g_kl);
    cudaGetSymbolAddress((void**)&vhp, g_vh);
    cudaGetSymbolAddress((void**)&vlp, g_vl);
    cudaGetSymbolAddress((void**)&zhp, g_zh);
    cudaGetSymbolAddress((void**)&zlp, g_zl);

    cudaFuncSetAttribute(gemm128, cudaFuncAttributeMaxDynamicSharedMemorySize,
                         G_SMEM);

    dim3 cgrid(DM_ / 32, DM_ / 32);
    dim3 cblk(32, 8);

    // split x + transpose/split all weights
    conv_split<<<BT_ * DM_ / 1024, 256>>>(x, ahp, alp);
    conv_T<<<cgrid, cblk>>>(Wq, wth,                 wtl);
    conv_T<<<cgrid, cblk>>>(Wk, wth + DM_ * DM_,     wtl + DM_ * DM_);
    conv_T<<<cgrid, cblk>>>(Wv, wth + 2 * DM_ * DM_, wtl + 2 * DM_ * DM_);

    // fused QKV GEMM: 24 x 32 CTAs
    gemm128<<<dim3(24, BT_ / 128), 256, G_SMEM>>>(ahp, alp, wth, wtl, qp, kp, vp);

    rope_split<<<BT_ * DM_ / 512, 256>>>(qp, kp, vp, cs, sn,
                                         qhp, qlp, khp, klp, vhp, vlp);

    attn_mma<<<dim3(16, B_ * H_), 256, ATT_SMEM>>>(qhp, qlp, khp, klp,
                                                   vhp, vlp, zhp, zlp);

    // out = z Wo
    conv_T<<<cgrid, cblk>>>(Wo, wth, wtl);
    gemm128<<<dim3(8, BT_ / 128), 256, G_SMEM>>>(zhp, zlp, wth, wtl, out, out, out);
}

// round 6
// speedup vs baseline: 2.9678x; 1.1611x over previous
#include <cuda_runtime.h>
#include <cuda_bf16.h>
#include <cstdint>

#define B_   2
#define T_   2048
#define DM_  1024
#define H_   16
#define DH_  64
#define BT_  (B_ * T_)   // 4096

// Scratch (allocation-free rule: device globals)
__device__ __nv_bfloat16 g_ah[BT_ * DM_], g_al[BT_ * DM_];       // x hi/lo
__device__ __nv_bfloat16 g_wth[4 * DM_ * DM_], g_wtl[4 * DM_ * DM_]; // W^T hi/lo (q,k,v,o)
__device__ __nv_bfloat16 g_qh[BT_ * DM_], g_ql[BT_ * DM_];
__device__ __nv_bfloat16 g_kh[BT_ * DM_], g_kl[BT_ * DM_];
__device__ __nv_bfloat16 g_vh[BT_ * DM_], g_vl[BT_ * DM_];
__device__ __nv_bfloat16 g_zh[BT_ * DM_], g_zl[BT_ * DM_];

// ===========================================================================
// Warp-MMA + cp.async helpers (baseline PTX — no tcgen05 on this harness)
// ===========================================================================
__device__ __forceinline__ uint32_t smem_u32(const void* p) {
    uint32_t a;
    asm("{ .reg .u64 t; cvta.to.shared.u64 t, %1; cvt.u32.u64 %0, t; }"
        : "=r"(a) : "l"(p));
    return a;
}

__device__ __forceinline__ void ldsm4(uint32_t* r, uint32_t addr) {
    asm volatile("ldmatrix.sync.aligned.m8n8.x4.shared.b16 {%0,%1,%2,%3}, [%4];"
                 : "=r"(r[0]), "=r"(r[1]), "=r"(r[2]), "=r"(r[3]) : "r"(addr));
}
__device__ __forceinline__ void ldsm4t(uint32_t* r, uint32_t addr) {
    asm volatile("ldmatrix.sync.aligned.m8n8.x4.trans.shared.b16 {%0,%1,%2,%3}, [%4];"
                 : "=r"(r[0]), "=r"(r[1]), "=r"(r[2]), "=r"(r[3]) : "r"(addr));
}

__device__ __forceinline__ void mma16816(float* c, const uint32_t* a,
                                         const uint32_t* b) {
    asm volatile(
        "mma.sync.aligned.m16n8k16.row.col.f32.bf16.bf16.f32 "
        "{%0,%1,%2,%3}, {%4,%5,%6,%7}, {%8,%9}, {%0,%1,%2,%3};"
        : "+f"(c[0]), "+f"(c[1]), "+f"(c[2]), "+f"(c[3])
        : "r"(a[0]), "r"(a[1]), "r"(a[2]), "r"(a[3]), "r"(b[0]), "r"(b[1]));
}

#define CP_ASYNC16(dst, src) \
    asm volatile("cp.async.cg.shared.global [%0], [%1], 16;" :: "r"(dst), "l"(src))
#define CP_COMMIT() asm volatile("cp.async.commit_group;")
#define CP_WAIT1()  asm volatile("cp.async.wait_group 1;")
#define CP_WAIT0()  asm volatile("cp.async.wait_group 0;")

// split pair (x,y) into bf16 hi/lo packed regs
__device__ __forceinline__ void split2(float x, float y, uint32_t& hi, uint32_t& lo) {
    __nv_bfloat162 h = __floats2bfloat162_rn(x, y);
    float hx = __bfloat162float(h.x), hy = __bfloat162float(h.y);
    __nv_bfloat162 l = __floats2bfloat162_rn(x - hx, y - hy);
    hi = *(uint32_t*)&h;
    lo = *(uint32_t*)&l;
}

// ===========================================================================
// Conversion kernels
// ===========================================================================
__global__ void conv_split(const float* __restrict__ in,
                           __nv_bfloat16* __restrict__ hi,
                           __nv_bfloat16* __restrict__ lo) {
    int i = (blockIdx.x * 256 + threadIdx.x) * 4;
    float4 v = *(const float4*)(in + i);
    uint32_t h0, l0, h1, l1;
    split2(v.x, v.y, h0, l0);
    split2(v.z, v.w, h1, l1);
    *(uint2*)(hi + i) = make_uint2(h0, h1);
    *(uint2*)(lo + i) = make_uint2(l0, l1);
}

// 4 weight matrices [K,N] row-major -> W^T hi/lo [N,K] into 4 slabs
__global__ void conv_T4(const float* __restrict__ W0, const float* __restrict__ W1,
                        const float* __restrict__ W2, const float* __restrict__ W3,
                        __nv_bfloat16* __restrict__ th, __nv_bfloat16* __restrict__ tl)
{
    __shared__ float t[32][33];
    const float* W = (blockIdx.z == 0) ? W0 : (blockIdx.z == 1) ? W1
                   : (blockIdx.z == 2) ? W2 : W3;
    const size_t slab = (size_t)blockIdx.z * DM_ * DM_;
    const int n0 = blockIdx.x * 32, k0 = blockIdx.y * 32;
    const int tx = threadIdx.x, ty = threadIdx.y;   // (32, 8)
    #pragma unroll
    for (int r = 0; r < 4; r++)
        t[ty * 4 + r][tx] = W[(size_t)(k0 + ty * 4 + r) * DM_ + n0 + tx];
    __syncthreads();
    #pragma unroll
    for (int r = 0; r < 4; r++) {
        float v = t[tx][ty * 4 + r];
        __nv_bfloat16 h = __float2bfloat16(v);
        __nv_bfloat16 l = __float2bfloat16(v - __bfloat162float(h));
        size_t o = slab + (size_t)(n0 + ty * 4 + r) * DM_ + k0 + tx;
        th[o] = h;
        tl[o] = l;
    }
}

// ===========================================================================
// bf16x2-split GEMM, 128x128 tile, BK=32, cp.async 2-stage, 2 CTA/SM.
// MODE 0: QKV (widx = blockIdx.x>>3 in 0..2) — fused RoPE+split epilogue
//         writing qh/ql, kh/kl, vh/vl bf16 directly.
// MODE 1: out-proj (widx = 3), fp32 epilogue to Cf.
// ===========================================================================
#define GP      80                    // smem row pitch
#define TSZ     (128 * GP)            // 10240 B per operand tile
#define STG     (4 * TSZ)             // 40960 B per stage
#define G_SMEM  (2 * STG)             // 81920 B

template<int MODE>
__global__ __launch_bounds__(256, 2) void gemm128(
    const __nv_bfloat16* __restrict__ Ah, const __nv_bfloat16* __restrict__ Al,
    const __nv_bfloat16* __restrict__ Bh, const __nv_bfloat16* __restrict__ Bl,
    const float* __restrict__ cs, const float* __restrict__ sn,
    float* __restrict__ Cf,
    __nv_bfloat16* __restrict__ qh, __nv_bfloat16* __restrict__ ql,
    __nv_bfloat16* __restrict__ kh, __nv_bfloat16* __restrict__ kl,
    __nv_bfloat16* __restrict__ vh, __nv_bfloat16* __restrict__ vl)
{
    extern __shared__ __align__(16) char sm[];
    const int tid  = threadIdx.x;
    const int wid  = tid >> 5;
    const int lane = tid & 31;
    const int wm   = wid & 3;
    const int wn   = wid >> 2;
    const int widx = (MODE == 0) ? (blockIdx.x >> 3) : 3;
    const int n0   = (blockIdx.x & 7) * 128;
    const int m0   = blockIdx.y * 128;
    const uint32_t sb = smem_u32(sm);

    const __nv_bfloat16* src[4] = {
        Ah + (size_t)m0 * DM_, Al + (size_t)m0 * DM_,
        Bh + (size_t)widx * DM_ * DM_ + (size_t)n0 * DM_,
        Bl + (size_t)widx * DM_ * DM_ + (size_t)n0 * DM_ };

    const int row = tid >> 2;          // 0..63
    const int cg  = tid & 3;           // 16B chunk in BK row

    #define ISSUE(st_, k0_)                                                    \
        {                                                                      \
            uint32_t d0 = sb + (st_) * STG + row * GP + cg * 16;               \
            _Pragma("unroll")                                                  \
            for (int t = 0; t < 4; t++) {                                      \
                const __nv_bfloat16* g = src[t] + (size_t)row * DM_ + (k0_) + cg * 8; \
                CP_ASYNC16(d0 + t * TSZ,           g);                         \
                CP_ASYNC16(d0 + t * TSZ + 64 * GP, g + (size_t)64 * DM_);      \
            }                                                                  \
            CP_COMMIT();                                                       \
        }

    const uint32_t a_off = (uint32_t)((lane & 15) * GP + (lane >> 4) * 16);
    const uint32_t b_off = (uint32_t)((((lane >> 4) * 8) + (lane & 7)) * GP +
                                      ((lane >> 3) & 1) * 16);

    float acc[2][8][4];
    #pragma unroll
    for (int i = 0; i < 2; i++)
        #pragma unroll
        for (int j = 0; j < 8; j++)
            #pragma unroll
            for (int l = 0; l < 4; l++) acc[i][j][l] = 0.f;

    ISSUE(0, 0);
    ISSUE(1, 32);

    const int NIT = DM_ / 32;   // 32
    for (int c = 0; c < NIT; c++) {
        if (c + 1 < NIT) { CP_WAIT1(); } else { CP_WAIT0(); }
        __syncthreads();

        const uint32_t stb = sb + (c & 1) * STG;
        #pragma unroll
        for (int ks = 0; ks < 2; ks++) {
            uint32_t ahf[2][4], alf[2][4];
            #pragma unroll
            for (int mt = 0; mt < 2; mt++) {
                uint32_t ab = stb + (uint32_t)((wm * 32 + mt * 16) * GP + ks * 32) + a_off;
                ldsm4(ahf[mt], ab);
                ldsm4(alf[mt], ab + TSZ);
            }
            #pragma unroll
            for (int nt = 0; nt < 4; nt++) {
                uint32_t bb = stb + 2 * TSZ +
                              (uint32_t)((wn * 64 + nt * 16) * GP + ks * 32) + b_off;
                uint32_t th[4], tl[4];
                ldsm4(th, bb);
                ldsm4(tl, bb + TSZ);
                #pragma unroll
                for (int mt = 0; mt < 2; mt++) {
                    mma16816(acc[mt][2*nt],   ahf[mt], th);
                    mma16816(acc[mt][2*nt],   ahf[mt], tl);
                    mma16816(acc[mt][2*nt],   alf[mt], th);
                    mma16816(acc[mt][2*nt+1], ahf[mt], th + 2);
                    mma16816(acc[mt][2*nt+1], ahf[mt], tl + 2);
                    mma16816(acc[mt][2*nt+1], alf[mt], th + 2);
                }
            }
        }
        __syncthreads();
        if (c + 2 < NIT) { ISSUE((c & 1), (c + 2) * 32); }
    }

    // ---- epilogue ----
    if (MODE == 1) {
        #pragma unroll
        for (int mt = 0; mt < 2; mt++) {
            int m = m0 + wm * 32 + mt * 16 + (lane >> 2);
            #pragma unroll
            for (int nt = 0; nt < 8; nt++) {
                int n = n0 + wn * 64 + nt * 8 + (lane & 3) * 2;
                *(float2*)(Cf + (size_t)m * DM_ + n) =
                    make_float2(acc[mt][nt][0], acc[mt][nt][1]);
                *(float2*)(Cf + (size_t)(m + 8) * DM_ + n) =
                    make_float2(acc[mt][nt][2], acc[mt][nt][3]);
            }
        }
    } else {
        __nv_bfloat16* dh = (widx == 0) ? qh : (widx == 1) ? kh : vh;
        __nv_bfloat16* dl = (widx == 0) ? ql : (widx == 1) ? kl : vl;
        #pragma unroll
        for (int mt = 0; mt < 2; mt++) {
            int m  = m0 + wm * 32 + mt * 16 + (lane >> 2);
            int t0 = m & (T_ - 1);
            int t1 = (m + 8) & (T_ - 1);
            #pragma unroll
            for (int nt = 0; nt < 8; nt++) {
                int n = n0 + wn * 64 + nt * 8 + (lane & 3) * 2;
                float e0 = acc[mt][nt][0], o0 = acc[mt][nt][1];
                float e1 = acc[mt][nt][2], o1 = acc[mt][nt][3];
                if (widx <= 1) {       // rope on q, k (scale q by 1/8)
                    int i = (n & 63) >> 1;
                    float c0 = __ldg(cs + t0 * 32 + i), s0 = __ldg(sn + t0 * 32 + i);
                    float c1 = __ldg(cs + t1 * 32 + i), s1 = __ldg(sn + t1 * 32 + i);
                    float sc = (widx == 0) ? 0.125f : 1.f;
                    float a0 = (e0 * c0 - o0 * s0) * sc, b0 = (e0 * s0 + o0 * c0) * sc;
                    float a1 = (e1 * c1 - o1 * s1) * sc, b1 = (e1 * s1 + o1 * c1) * sc;
                    e0 = a0; o0 = b0; e1 = a1; o1 = b1;
                }
                uint32_t h32, l32;
                split2(e0, o0, h32, l32);
                *(uint32_t*)(dh + (size_t)m * DM_ + n) = h32;
                *(uint32_t*)(dl + (size_t)m * DM_ + n) = l32;
                split2(e1, o1, h32, l32);
                *(uint32_t*)(dh + (size_t)(m + 8) * DM_ + n) = h32;
                *(uint32_t*)(dl + (size_t)(m + 8) * DM_ + n) = l32;
            }
        }
    }
    #undef ISSUE
}

// ===========================================================================
// Tensor-core flash attention (bf16 hi/lo split, causal).
// cp.async 2-stage double-buffered K/V tiles.
// ===========================================================================
#define PIT   144
#define KL_O  9216
#define VH_O  18432
#define VL_O  27648
#define AST   36864                 // stage size
#define ATT_SMEM (2 * AST)          // 73728

__global__ __launch_bounds__(256) void attn_mma(
    const __nv_bfloat16* __restrict__ qh, const __nv_bfloat16* __restrict__ ql,
    const __nv_bfloat16* __restrict__ kh, const __nv_bfloat16* __restrict__ kl,
    const __nv_bfloat16* __restrict__ vh, const __nv_bfloat16* __restrict__ vl,
    __nv_bfloat16* __restrict__ zh, __nv_bfloat16* __restrict__ zl)
{
    extern __shared__ __align__(16) char sm[];
    const int tid  = threadIdx.x;
    const int lane = tid & 31;
    const int wq   = tid >> 5;
    const int qi   = 15 - blockIdx.x;
    const int bh_  = blockIdx.y;
    const int b    = bh_ >> 4;
    const int h    = bh_ & 15;
    const int q0   = qi * 128;
    const int bT   = b * T_;
    const uint32_t sb = smem_u32(sm);
    const size_t hcol = (size_t)h * DH_;

    // ---- stage Q (hi/lo) through smem, extract A-fragments ----
    {
        int r = tid >> 3, c = tid & 7;
        #pragma unroll
        for (int i = 0; i < 4; i++) {
            int row = r + i * 32;
            size_t g = ((size_t)(bT + q0 + row)) * DM_ + hcol + c * 8;
            *(uint4*)(sm + row * PIT + c * 16)         = *(const uint4*)(qh + g);
            *(uint4*)(sm + 18432 + row * PIT + c * 16) = *(const uint4*)(ql + g);
        }
    }
    __syncthreads();

    uint32_t qfh[4][4], qfl[4][4];
    {
        const uint32_t a_off = (lane & 15) * PIT + (lane >> 4) * 16;
        #pragma unroll
        for (int ks = 0; ks < 4; ks++) {
            ldsm4(qfh[ks], sb + (wq * 16) * PIT + ks * 32 + a_off);
            ldsm4(qfl[ks], sb + 18432 + (wq * 16) * PIT + ks * 32 + a_off);
        }
    }
    __syncthreads();   // Q reads done; smem reusable for K/V stages

    const int nkt = 2 * qi + 2;

    // cp.async K/V tile loader (stage st_, key offset k0_)
    #define AISSUE(st_, k0_)                                                   \
        {                                                                      \
            int r = tid >> 3, cc = tid & 7;                                    \
            uint32_t d = sb + (st_) * AST + r * PIT + cc * 16;                 \
            size_t g = ((size_t)(bT + (k0_) + r)) * DM_ + hcol + cc * 8;       \
            CP_ASYNC16(d,                   kh + g);                           \
            CP_ASYNC16(d + 32 * PIT,        kh + g + 32 * DM_);                \
            CP_ASYNC16(d + KL_O,            kl + g);                           \
            CP_ASYNC16(d + KL_O + 32 * PIT, kl + g + 32 * DM_);                \
            CP_ASYNC16(d + VH_O,            vh + g);                           \
            CP_ASYNC16(d + VH_O + 32 * PIT, vh + g + 32 * DM_);                \
            CP_ASYNC16(d + VL_O,            vl + g);                           \
            CP_ASYNC16(d + VL_O + 32 * PIT, vl + g + 32 * DM_);                \
            CP_COMMIT();                                                       \
        }

    AISSUE(0, 0);
    if (nkt > 1) AISSUE(1, 64);

    float o[8][4];
    #pragma unroll
    for (int i = 0; i < 8; i++)
        #pragma unroll
        for (int j = 0; j < 4; j++) o[i][j] = 0.f;
    float m_lo = -1e30f, m_hi = -1e30f, l_lo = 0.f, l_hi = 0.f;

    const uint32_t k_off = ((lane >> 4) * 8 + (lane & 7)) * PIT + ((lane >> 3) & 1) * 16;
    const uint32_t v_off = (lane & 7) * PIT + ((lane >> 3) & 1) * 8 * PIT + (lane >> 4) * 16;
    const int qg_lo = q0 + wq * 16 + (lane >> 2);
    const int qg_hi = qg_lo + 8;

    for (int kt = 0; kt < nkt; kt++) {
        const int k0 = kt * 64;
        if (kt + 1 < nkt) { CP_WAIT1(); } else { CP_WAIT0(); }
        __syncthreads();
        const uint32_t stb = sb + (kt & 1) * AST;

        // ---- S = Q K^T (3-pass split) ----
        float sf[8][4];
        #pragma unroll
        for (int i = 0; i < 8; i++)
            #pragma unroll
            for (int j = 0; j < 4; j++) sf[i][j] = 0.f;

        #pragma unroll
        for (int ks = 0; ks < 4; ks++) {
            #pragma unroll
            for (int nt2 = 0; nt2 < 4; nt2++) {
                uint32_t th[4], tl[4];
                ldsm4(th, stb + (nt2 * 16) * PIT + ks * 32 + k_off);
                ldsm4(tl, stb + KL_O + (nt2 * 16) * PIT + ks * 32 + k_off);
                mma16816(sf[2*nt2],   qfh[ks], th);
                mma16816(sf[2*nt2],   qfh[ks], tl);
                mma16816(sf[2*nt2],   qfl[ks], th);
                mma16816(sf[2*nt2+1], qfh[ks], th + 2);
                mma16816(sf[2*nt2+1], qfh[ks], tl + 2);
                mma16816(sf[2*nt2+1], qfl[ks], th + 2);
            }
        }

        if (kt >= nkt - 2) {
            #pragma unroll
            for (int nt = 0; nt < 8; nt++) {
                int kg = k0 + nt * 8 + (lane & 3) * 2;
                if (kg     > qg_lo) sf[nt][0] = -1e30f;
                if (kg + 1 > qg_lo) sf[nt][1] = -1e30f;
                if (kg     > qg_hi) sf[nt][2] = -1e30f;
                if (kg + 1 > qg_hi) sf[nt][3] = -1e30f;
            }
        }

        // ---- online softmax ----
        float mx_lo = sf[0][0], mx_hi = sf[0][2];
        #pragma unroll
        for (int nt = 0; nt < 8; nt++) {
            mx_lo = fmaxf(mx_lo, fmaxf(sf[nt][0], sf[nt][1]));
            mx_hi = fmaxf(mx_hi, fmaxf(sf[nt][2], sf[nt][3]));
        }
        mx_lo = fmaxf(mx_lo, __shfl_xor_sync(0xffffffffu, mx_lo, 1));
        mx_lo = fmaxf(mx_lo, __shfl_xor_sync(0xffffffffu, mx_lo, 2));
        mx_hi = fmaxf(mx_hi, __shfl_xor_sync(0xffffffffu, mx_hi, 1));
        mx_hi = fmaxf(mx_hi, __shfl_xor_sync(0xffffffffu, mx_hi, 2));

        float nm_lo = fmaxf(m_lo, mx_lo), nm_hi = fmaxf(m_hi, mx_hi);
        float cr_lo = __expf(m_lo - nm_lo), cr_hi = __expf(m_hi - nm_hi);
        m_lo = nm_lo; m_hi = nm_hi;

        float rs_lo = 0.f, rs_hi = 0.f;
        #pragma unroll
        for (int nt = 0; nt < 8; nt++) {
            sf[nt][0] = __expf(sf[nt][0] - nm_lo); rs_lo += sf[nt][0];
            sf[nt][1] = __expf(sf[nt][1] - nm_lo); rs_lo += sf[nt][1];
            sf[nt][2] = __expf(sf[nt][2] - nm_hi); rs_hi += sf[nt][2];
            sf[nt][3] = __expf(sf[nt][3] - nm_hi); rs_hi += sf[nt][3];
        }
        rs_lo += __shfl_xor_sync(0xffffffffu, rs_lo, 1);
        rs_lo += __shfl_xor_sync(0xffffffffu, rs_lo, 2);
        rs_hi += __shfl_xor_sync(0xffffffffu, rs_hi, 1);
        rs_hi += __shfl_xor_sync(0xffffffffu, rs_hi, 2);
        l_lo = l_lo * cr_lo + rs_lo;
        l_hi = l_hi * cr_hi + rs_hi;

        #pragma unroll
        for (int nt = 0; nt < 8; nt++) {
            o[nt][0] *= cr_lo; o[nt][1] *= cr_lo;
            o[nt][2] *= cr_hi; o[nt][3] *= cr_hi;
        }

        // ---- pack P -> bf16 hi/lo A-operands in registers ----
        uint32_t pfh[4][4], pfl[4][4];
        #pragma unroll
        for (int j = 0; j < 4; j++) {
            split2(sf[2*j][0],   sf[2*j][1],   pfh[j][0], pfl[j][0]);
            split2(sf[2*j][2],   sf[2*j][3],   pfh[j][1], pfl[j][1]);
            split2(sf[2*j+1][0], sf[2*j+1][1], pfh[j][2], pfl[j][2]);
            split2(sf[2*j+1][2], sf[2*j+1][3], pfh[j][3], pfl[j][3]);
        }

        // ---- O += P V ----
        #pragma unroll
        for (int j = 0; j < 4; j++) {
            #pragma unroll
            for (int d2 = 0; d2 < 4; d2++) {
                uint32_t th[4], tl[4];
                ldsm4t(th, stb + VH_O + (j * 16) * PIT + d2 * 32 + v_off);
                ldsm4t(tl, stb + VL_O + (j * 16) * PIT + d2 * 32 + v_off);
                mma16816(o[2*d2],   pfh[j], th);
                mma16816(o[2*d2],   pfh[j], tl);
                mma16816(o[2*d2],   pfl[j], th);
                mma16816(o[2*d2+1], pfh[j], th + 2);
                mma16816(o[2*d2+1], pfh[j], tl + 2);
                mma16816(o[2*d2+1], pfl[j], th + 2);
            }
        }

        __syncthreads();
        if (kt + 2 < nkt) { AISSUE((kt & 1), (kt + 2) * 64); }
    }
    #undef AISSUE

    // ---- epilogue: normalize, split, write zh/zl ----
    float il_lo = 1.f / l_lo, il_hi = 1.f / l_hi;
    size_t out_lo = ((size_t)(bT + qg_lo)) * DM_ + hcol + (lane & 3) * 2;
    #pragma unroll
    for (int nt = 0; nt < 8; nt++) {
        uint32_t h32, l32;
        split2(o[nt][0] * il_lo, o[nt][1] * il_lo, h32, l32);
        *(uint32_t*)(zh + out_lo + nt * 8) = h32;
        *(uint32_t*)(zl + out_lo + nt * 8) = l32;
        split2(o[nt][2] * il_hi, o[nt][3] * il_hi, h32, l32);
        *(uint32_t*)(zh + out_lo + 8 * DM_ + nt * 8) = h32;
        *(uint32_t*)(zl + out_lo + 8 * DM_ + nt * 8) = l32;
    }
}

// ---------------------------------------------------------------------------
extern "C" void kernel_launch(void* const* d_in, const int* in_sizes, int n_in,
                              void* d_out, int out_size)
{
    const float* x  = (const float*)d_in[0];
    const float* cs = (const float*)d_in[1];
    const float* sn = (const float*)d_in[2];
    const float* Wq = (const float*)d_in[3];
    const float* Wk = (const float*)d_in[4];
    const float* Wv = (const float*)d_in[5];
    const float* Wo = (const float*)d_in[6];
    float* out = (float*)d_out;

    __nv_bfloat16 *ahp, *alp, *wth, *wtl;
    __nv_bfloat16 *qhp, *qlp, *khp, *klp, *vhp, *vlp, *zhp, *zlp;
    cudaGetSymbolAddress((void**)&ahp, g_ah);
    cudaGetSymbolAddress((void**)&alp, g_al);
    cudaGetSymbolAddress((void**)&wth, g_wth);
    cudaGetSymbolAddress((void**)&wtl, g_wtl);
    cudaGetSymbolAddress((void**)&qhp, g_qh);
    cudaGetSymbolAddress((void**)&qlp, g_ql);
    cudaGetSymbolAddress((void**)&khp, g_kh);
    cudaGetSymbolAddress((void**)&klp, g_kl);
    cudaGetSymbolAddress((void**)&vhp, g_vh);
    cudaGetSymbolAddress((void**)&vlp, g_vl);
    cudaGetSymbolAddress((void**)&zhp, g_zh);
    cudaGetSymbolAddress((void**)&zlp, g_zl);

    cudaFuncSetAttribute(gemm128<0>, cudaFuncAttributeMaxDynamicSharedMemorySize, G_SMEM);
    cudaFuncSetAttribute(gemm128<1>, cudaFuncAttributeMaxDynamicSharedMemorySize, G_SMEM);
    cudaFuncSetAttribute(attn_mma, cudaFuncAttributeMaxDynamicSharedMemorySize, ATT_SMEM);

    // split x; transpose/split all 4 weights in one launch
    conv_split<<<BT_ * DM_ / 1024, 256>>>(x, ahp, alp);
    conv_T4<<<dim3(DM_ / 32, DM_ / 32, 4), dim3(32, 8)>>>(Wq, Wk, Wv, Wo, wth, wtl);

    // fused QKV GEMM + RoPE + split epilogue
    gemm128<0><<<dim3(24, BT_ / 128), 256, G_SMEM>>>(
        ahp, alp, wth, wtl, cs, sn, nullptr,
        qhp, qlp, khp, klp, vhp, vlp);

    attn_mma<<<dim3(16, B_ * H_), 256, ATT_SMEM>>>(qhp, qlp, khp, klp,
                                                   vhp, vlp, zhp, zlp);

    // out = z Wo
    gemm128<1><<<dim3(8, BT_ / 128), 256, G_SMEM>>>(
        zhp, zlp, wth, wtl, cs, sn, out,
        nullptr, nullptr, nullptr, nullptr, nullptr, nullptr);
}